// round 8
// baseline (speedup 1.0000x reference)
#include <cuda_runtime.h>
#include <cuda_bf16.h>

// Problem constants
#define BB  4
#define CX  16
#define CA  8
#define C1  16
#define NN  1024
#define DD  64
#define NEGINF (-3.402823466e38f)

// 0.02*sigmoid(z) = 0.01 + 0.01*tanh(z/2); z = S*mm/sqrt(10)
// -> store S' = S * 0.5/sqrt(10), A' = Amean + 0.01; out = fma(0.01, tanh(S'*mm), A')
#define SSCALE 0.15811388300841898f

// Scratch (static __device__ arrays; no dynamic allocation)
__device__ __align__(16) __nv_bfloat16 g_Sp[8u * BB * NN * NN];    // 67 MB partial S (bf16)
__device__ __align__(16) float g_SA[2u * BB * NN * NN];            // 33.6 MB (S',A') interleaved
__device__ __align__(16) __nv_bfloat16 g_xbf[BB * CX * NN * DD];   // 8.4 MB
__device__ __align__(16) __nv_bfloat16 g_mbf[BB * C1 * NN * DD];   // 8.4 MB

// ---------------------------------------------------------------------------
// PTX helpers
// ---------------------------------------------------------------------------
__device__ __forceinline__ unsigned sptr(const void* p) {
    return (unsigned)__cvta_generic_to_shared(p);
}

__device__ __forceinline__ void ldsm4(unsigned a[4], unsigned addr) {
    asm volatile("ldmatrix.sync.aligned.m8n8.x4.shared.b16 {%0,%1,%2,%3}, [%4];"
                 : "=r"(a[0]), "=r"(a[1]), "=r"(a[2]), "=r"(a[3]) : "r"(addr));
}

__device__ __forceinline__ void mma16816(float c[4], const unsigned a[4],
                                         unsigned b0, unsigned b1) {
    asm volatile(
        "mma.sync.aligned.m16n8k16.row.col.f32.bf16.bf16.f32 "
        "{%0,%1,%2,%3}, {%4,%5,%6,%7}, {%8,%9}, {%0,%1,%2,%3};"
        : "+f"(c[0]), "+f"(c[1]), "+f"(c[2]), "+f"(c[3])
        : "r"(a[0]), "r"(a[1]), "r"(a[2]), "r"(a[3]), "r"(b0), "r"(b1));
}

__device__ __forceinline__ void cpasync16(unsigned dst, const void* src) {
    asm volatile("cp.async.cg.shared.global [%0], [%1], 16;" :: "r"(dst), "l"(src));
}
#define CP_COMMIT() asm volatile("cp.async.commit_group;")
#define CP_WAIT1()  asm volatile("cp.async.wait_group 1;")
#define CP_WAIT0()  asm volatile("cp.async.wait_group 0;")

__device__ __forceinline__ float tanhap(float x) {
    float r;
    asm("tanh.approx.f32 %0, %1;" : "=f"(r) : "f"(x));
    return r;
}

__device__ __forceinline__ unsigned packbf2(float a, float b) {
    __nv_bfloat162 h = __floats2bfloat162_rn(a, b);
    return *reinterpret_cast<unsigned*>(&h);
}

// ---------------------------------------------------------------------------
// Swizzled bf16 tiles: [rows][64] bf16, 128B/row; 16B chunk' = chunk ^ (row&7)
// ---------------------------------------------------------------------------
__device__ __forceinline__ void pf_tile128(const __nv_bfloat16* src,
                                           __nv_bfloat16* dst, int tid) {
#pragma unroll
    for (int q = 0; q < 4; q++) {
        int id = tid + q * 256;
        int r = id >> 3, cc = id & 7;
        cpasync16(sptr(dst + r * 64 + ((cc ^ (r & 7)) << 3)), src + r * 64 + cc * 8);
    }
}

__device__ __forceinline__ void pf_tile64(const __nv_bfloat16* src,
                                          __nv_bfloat16* dst, int tid) {
#pragma unroll
    for (int q = 0; q < 2; q++) {
        int id = tid + q * 256;
        int r = id >> 3, cc = id & 7;
        cpasync16(sptr(dst + r * 64 + ((cc ^ (r & 7)) << 3)), src + r * 64 + cc * 8);
    }
}

// A fragments for a 16-row slice, cached in regs
__device__ __forceinline__ void load_afrag(const __nv_bfloat16* xi16, int lane,
                                           unsigned a[4][4]) {
    const int ar = (lane & 7) + (((lane >> 3) & 1) << 3);
    const int ak8 = lane >> 4;
#pragma unroll
    for (int ks = 0; ks < 4; ks++)
        ldsm4(a[ks], sptr(xi16 + ar * 64 + (((2 * ks + ak8) ^ (ar & 7)) << 3)));
}

// acc[8] += A(16x64) * B(rows n0..n0+15 of 64x64 tile)^T
__device__ __forceinline__ void subtile_mma(const __nv_bfloat16* bt, int n0, int lane,
                                            const unsigned a[4][4], float acc[8]) {
    const int m = lane >> 3;
    const int br = n0 + (lane & 7) + ((m >> 1) << 3);
    const int bk8 = m & 1;
#pragma unroll
    for (int ks = 0; ks < 4; ks++) {
        unsigned b[4];
        ldsm4(b, sptr(bt + br * 64 + (((2 * ks + bk8) ^ (br & 7)) << 3)));
        mma16816(acc, a[ks], b[0], b[1]);
        mma16816(acc + 4, a[ks], b[2], b[3]);
    }
}

// ---------------------------------------------------------------------------
// Prep: bf16 conversion of x and mask in one kernel
// ---------------------------------------------------------------------------
#define NX4 (BB * CX * NN * DD / 4)
#define NM4 (BB * C1 * NN * DD / 4)
__global__ void k_conv(const float* __restrict__ x, const float* __restrict__ mask) {
    int idx = blockIdx.x * blockDim.x + threadIdx.x;
    const float4* src;
    uint2* dst;
    int i;
    if (idx < NX4) { src = (const float4*)x; dst = (uint2*)g_xbf; i = idx; }
    else if (idx < NX4 + NM4) { src = (const float4*)mask; dst = (uint2*)g_mbf; i = idx - NX4; }
    else return;
    float4 v = src[i];
    uint2 u;
    u.x = packbf2(v.x, v.y);
    u.y = packbf2(v.z, v.w);
    dst[i] = u;
}

// ---------------------------------------------------------------------------
// k_S3: partial S for 2 channels, 64-row tiles.
// grid (itile=16, cg=8, b=4) = 512 blocks, 256 thr.
// ---------------------------------------------------------------------------
#define KS3_SMEM (2*64*64*2 + 2*2*64*64*2 + 2*64*4 + 2*64*2*4 + 2*64*4)

__global__ void __launch_bounds__(256, 3) k_S3() {
    extern __shared__ char sm[];
    __nv_bfloat16* xi  = (__nv_bfloat16*)sm;            // [2ch][64*64]
    __nv_bfloat16* xjb = xi + 2 * 64 * 64;              // [2buf][2ch][64*64]
    float* P  = (float*)(xjb + 2 * 2 * 64 * 64);        // [2][64]
    float* Zw = P + 2 * 64;                             // [2][64][2]
    float* Zi = Zw + 2 * 64 * 2;                        // [2][64]

    const int tid = threadIdx.x, lane = tid & 31, w = tid >> 5;
    const int wr = w & 3, wc = w >> 2;
    const int itile = blockIdx.x, cg = blockIdx.y, b = blockIdx.z;

    const __nv_bfloat16* xc0 = g_xbf + (size_t)(b * CX + cg * 2) * NN * DD;
    const __nv_bfloat16* xc1 = xc0 + NN * DD;

    pf_tile64(xc0 + itile * 64 * 64, xi, tid);
    pf_tile64(xc1 + itile * 64 * 64, xi + 64 * 64, tid);
    CP_COMMIT();
    pf_tile64(xc0, xjb, tid);
    pf_tile64(xc1, xjb + 64 * 64, tid);
    CP_COMMIT();
    CP_WAIT1();
    __syncthreads();

    // P = ||row||^2 from bf16 values
    if (tid < 128) {
        int c = tid >> 6, r = tid & 63;
        const __nv_bfloat16* row = xi + c * 4096 + r * 64;
        float s = 0.f;
#pragma unroll
        for (int cc = 0; cc < 8; cc++) {
            const __nv_bfloat16* ch = row + ((cc ^ (r & 7)) << 3);
#pragma unroll
            for (int e = 0; e < 8; e++) {
                float v = __bfloat162float(ch[e]);
                s += v * v;
            }
        }
        P[c * 64 + r] = s;
    }
    __syncthreads();

    unsigned a0[4][4], a1[4][4];
    load_afrag(xi + wr * 16 * 64, lane, a0);
    load_afrag(xi + 4096 + wr * 16 * 64, lane, a1);

    const int lr0 = wr * 16 + (lane >> 2), lr1 = lr0 + 8;
    const float p00 = P[lr0], p01 = P[lr1], p10 = P[64 + lr0], p11 = P[64 + lr1];

    // ---- Pass Z ----
    float z00 = 0.f, z01 = 0.f, z10 = 0.f, z11 = 0.f;
    for (int jt = 0; jt < 16; jt++) {
        if (jt < 15) {
            __nv_bfloat16* nb = xjb + ((jt + 1) & 1) * 8192;
            pf_tile64(xc0 + (jt + 1) * 64 * 64, nb, tid);
            pf_tile64(xc1 + (jt + 1) * 64 * 64, nb + 4096, tid);
            CP_COMMIT(); CP_WAIT1();
        } else CP_WAIT0();
        __syncthreads();
        const __nv_bfloat16* bt = xjb + (jt & 1) * 8192;
#pragma unroll
        for (int nn = 0; nn < 2; nn++) {
            const int n0 = (wc * 2 + nn) * 16;
            {
                float acc[8] = {0.f, 0.f, 0.f, 0.f, 0.f, 0.f, 0.f, 0.f};
                subtile_mma(bt, n0, lane, a0, acc);
                z00 += __expf(acc[0] - p00) + __expf(acc[1] - p00)
                     + __expf(acc[4] - p00) + __expf(acc[5] - p00);
                z01 += __expf(acc[2] - p01) + __expf(acc[3] - p01)
                     + __expf(acc[6] - p01) + __expf(acc[7] - p01);
            }
            {
                float acc[8] = {0.f, 0.f, 0.f, 0.f, 0.f, 0.f, 0.f, 0.f};
                subtile_mma(bt + 4096, n0, lane, a1, acc);
                z10 += __expf(acc[0] - p10) + __expf(acc[1] - p10)
                     + __expf(acc[4] - p10) + __expf(acc[5] - p10);
                z11 += __expf(acc[2] - p11) + __expf(acc[3] - p11)
                     + __expf(acc[6] - p11) + __expf(acc[7] - p11);
            }
        }
        __syncthreads();
    }
    z00 += __shfl_xor_sync(0xffffffffu, z00, 1); z00 += __shfl_xor_sync(0xffffffffu, z00, 2);
    z01 += __shfl_xor_sync(0xffffffffu, z01, 1); z01 += __shfl_xor_sync(0xffffffffu, z01, 2);
    z10 += __shfl_xor_sync(0xffffffffu, z10, 1); z10 += __shfl_xor_sync(0xffffffffu, z10, 2);
    z11 += __shfl_xor_sync(0xffffffffu, z11, 1); z11 += __shfl_xor_sync(0xffffffffu, z11, 2);
    if ((lane & 3) == 0) {
        Zw[lr0 * 2 + wc]       = z00;
        Zw[lr1 * 2 + wc]       = z01;
        Zw[128 + lr0 * 2 + wc] = z10;
        Zw[128 + lr1 * 2 + wc] = z11;
    }
    __syncthreads();
    if (tid < 128) {
        int c = tid >> 6, r = tid & 63;
        Zi[c * 64 + r] = 1.f / (16.f * (Zw[c * 128 + r * 2] + Zw[c * 128 + r * 2 + 1]));
    }
    pf_tile64(xc0, xjb, tid);
    pf_tile64(xc1, xjb + 4096, tid);
    CP_COMMIT();
    __syncthreads();

    const float zi00 = Zi[lr0], zi01 = Zi[lr1];
    const float zi10 = Zi[64 + lr0], zi11 = Zi[64 + lr1];

    __nv_bfloat16* spBase = g_Sp + (size_t)(cg * BB + b) * NN * NN + (size_t)(itile * 64) * NN;

    for (int jt = 0; jt < 16; jt++) {
        if (jt < 15) {
            __nv_bfloat16* nb = xjb + ((jt + 1) & 1) * 8192;
            pf_tile64(xc0 + (jt + 1) * 64 * 64, nb, tid);
            pf_tile64(xc1 + (jt + 1) * 64 * 64, nb + 4096, tid);
            CP_COMMIT(); CP_WAIT1();
        } else CP_WAIT0();
        __syncthreads();
        const __nv_bfloat16* bt = xjb + (jt & 1) * 8192;

#pragma unroll
        for (int nn = 0; nn < 2; nn++) {
            const int n = wc * 2 + nn;
            float Sa[8];
#pragma unroll
            for (int k = 0; k < 8; k++) Sa[k] = 0.f;
            {
                float acc[8] = {0.f, 0.f, 0.f, 0.f, 0.f, 0.f, 0.f, 0.f};
                subtile_mma(bt, n * 16, lane, a0, acc);
                Sa[0] += __expf(acc[0] - p00) * zi00;
                Sa[1] += __expf(acc[1] - p00) * zi00;
                Sa[4] += __expf(acc[4] - p00) * zi00;
                Sa[5] += __expf(acc[5] - p00) * zi00;
                Sa[2] += __expf(acc[2] - p01) * zi01;
                Sa[3] += __expf(acc[3] - p01) * zi01;
                Sa[6] += __expf(acc[6] - p01) * zi01;
                Sa[7] += __expf(acc[7] - p01) * zi01;
            }
            {
                float acc[8] = {0.f, 0.f, 0.f, 0.f, 0.f, 0.f, 0.f, 0.f};
                subtile_mma(bt + 4096, n * 16, lane, a1, acc);
                Sa[0] += __expf(acc[0] - p10) * zi10;
                Sa[1] += __expf(acc[1] - p10) * zi10;
                Sa[4] += __expf(acc[4] - p10) * zi10;
                Sa[5] += __expf(acc[5] - p10) * zi10;
                Sa[2] += __expf(acc[2] - p11) * zi11;
                Sa[3] += __expf(acc[3] - p11) * zi11;
                Sa[6] += __expf(acc[6] - p11) * zi11;
                Sa[7] += __expf(acc[7] - p11) * zi11;
            }
            const int cb = jt * 64 + n * 16 + 2 * (lane & 3);
            *(unsigned*)(spBase + (size_t)lr0 * NN + cb)     = packbf2(Sa[0], Sa[1]);
            *(unsigned*)(spBase + (size_t)lr0 * NN + cb + 8) = packbf2(Sa[4], Sa[5]);
            *(unsigned*)(spBase + (size_t)lr1 * NN + cb)     = packbf2(Sa[2], Sa[3]);
            *(unsigned*)(spBase + (size_t)lr1 * NN + cb + 8) = packbf2(Sa[6], Sa[7]);
        }
        __syncthreads();
    }
}

// ---------------------------------------------------------------------------
// k_sreduce2: sum 8 bf16 partial S slices + mean of A over CA, write
// interleaved (S*SSCALE, Amean+0.01) pairs.
// ---------------------------------------------------------------------------
__global__ void k_sreduce2(const float* __restrict__ A) {
    int i = blockIdx.x * 256 + threadIdx.x;   // group of 4 elements
    const int per_b = NN * NN / 4;
    int b = i / per_b;
    int r = i - b * per_b;

    const uint2* sp = (const uint2*)g_Sp;
    float4 s = make_float4(0.f, 0.f, 0.f, 0.f);
#pragma unroll
    for (int g = 0; g < 8; g++) {
        uint2 u = sp[(size_t)(g * BB + b) * per_b + r];
        __nv_bfloat162 h0 = *reinterpret_cast<__nv_bfloat162*>(&u.x);
        __nv_bfloat162 h1 = *reinterpret_cast<__nv_bfloat162*>(&u.y);
        float2 f0 = __bfloat1622float2(h0);
        float2 f1 = __bfloat1622float2(h1);
        s.x += f0.x; s.y += f0.y; s.z += f1.x; s.w += f1.y;
    }
    const float4* ap = (const float4*)A + (size_t)b * CA * per_b + r;
    float4 a = ap[0];
#pragma unroll
    for (int ch = 1; ch < CA; ch++) {
        float4 v = ap[(size_t)ch * per_b];
        a.x += v.x; a.y += v.y; a.z += v.z; a.w += v.w;
    }
    float4 o1, o2;
    o1.x = s.x * SSCALE; o1.y = a.x * 0.125f + 0.01f;
    o1.z = s.y * SSCALE; o1.w = a.y * 0.125f + 0.01f;
    o2.x = s.z * SSCALE; o2.y = a.z * 0.125f + 0.01f;
    o2.z = s.w * SSCALE; o2.w = a.w * 0.125f + 0.01f;
    float4* out = (float4*)g_SA + (size_t)i * 2;
    out[0] = o1;
    out[1] = o2;
}

// ---------------------------------------------------------------------------
// k_mm: per (itile, c, b): GEMM + fused tanh elementwise + A_out write.
// grid (8, 16, 4) = 512 blocks, 3 blocks/SM -> 24 warps/SM for latency hiding.
// ---------------------------------------------------------------------------
#define KMM_SMEM (128*64*2 + 2*64*64*2)

__global__ void __launch_bounds__(256, 3) k_mm(float* __restrict__ outA) {
    extern __shared__ char sm[];
    __nv_bfloat16* mi  = (__nv_bfloat16*)sm;       // [128*64]
    __nv_bfloat16* mjb = mi + 128 * 64;            // [2][64*64]

    const int tid = threadIdx.x, lane = tid & 31, w = tid >> 5;
    const int itile = blockIdx.x, c = blockIdx.y, b = blockIdx.z;

    const __nv_bfloat16* mc = g_mbf + (size_t)(b * C1 + c) * NN * DD;
    const int lq = 2 * (lane & 3);

    pf_tile128(mc + itile * 128 * 64, mi, tid);
    pf_tile64(mc, mjb, tid);
    CP_COMMIT();
    CP_WAIT0();
    __syncthreads();

    unsigned a[4][4];
    load_afrag(mi + w * 16 * 64, lane, a);

    const int lr0 = w * 16 + (lane >> 2), lr1 = lr0 + 8;
    const int gr0 = itile * 128 + lr0, gr1 = itile * 128 + lr1;
    const float* SA0 = g_SA + ((size_t)b * NN + gr0) * NN * 2;
    const float* SA1 = g_SA + ((size_t)b * NN + gr1) * NN * 2;
    float* O0 = outA + ((size_t)(b * C1 + c) * NN + gr0) * NN;
    float* O1 = outA + ((size_t)(b * C1 + c) * NN + gr1) * NN;

    for (int jt = 0; jt < 16; jt++) {
        if (jt < 15) {
            pf_tile64(mc + (jt + 1) * 4096, mjb + ((jt + 1) & 1) * 4096, tid);
            CP_COMMIT();
            CP_WAIT1();
        } else CP_WAIT0();
        __syncthreads();
        const __nv_bfloat16* bt = mjb + (jt & 1) * 4096;

#pragma unroll
        for (int n = 0; n < 4; n++) {
            const int cb = jt * 64 + n * 16 + lq;
            const float4 q0 = *(const float4*)(SA0 + 2 * cb);
            const float4 q1 = *(const float4*)(SA0 + 2 * (cb + 8));
            const float4 q2 = *(const float4*)(SA1 + 2 * cb);
            const float4 q3 = *(const float4*)(SA1 + 2 * (cb + 8));

            float acc[8] = {0.f, 0.f, 0.f, 0.f, 0.f, 0.f, 0.f, 0.f};
            subtile_mma(bt, n * 16, lane, a, acc);

            float o0 = fmaf(0.01f, tanhap(q0.x * acc[0]), q0.y);
            float o1 = fmaf(0.01f, tanhap(q0.z * acc[1]), q0.w);
            float o4 = fmaf(0.01f, tanhap(q1.x * acc[4]), q1.y);
            float o5 = fmaf(0.01f, tanhap(q1.z * acc[5]), q1.w);
            float o2 = fmaf(0.01f, tanhap(q2.x * acc[2]), q2.y);
            float o3 = fmaf(0.01f, tanhap(q2.z * acc[3]), q2.w);
            float o6 = fmaf(0.01f, tanhap(q3.x * acc[6]), q3.y);
            float o7 = fmaf(0.01f, tanhap(q3.z * acc[7]), q3.w);

            *(float2*)(O0 + cb)     = make_float2(o0, o1);
            *(float2*)(O0 + cb + 8) = make_float2(o4, o5);
            *(float2*)(O1 + cb)     = make_float2(o2, o3);
            *(float2*)(O1 + cb + 8) = make_float2(o6, o7);
        }
        __syncthreads();
    }
}

// ---------------------------------------------------------------------------
// k_topk: warp per row. Phase 1 batch-loads the whole row (MLP=8), phase 2
// does the rare-branch top-5, then 32-lane merge + gather + max.
// ---------------------------------------------------------------------------
__device__ __forceinline__ void ins5(float x, int i, float v[5], int ix[5]) {
#pragma unroll
    for (int p = 0; p < 5; p++) {
        if (x > v[p]) {
            float tv = v[p]; v[p] = x; x = tv;
            int ti = ix[p]; ix[p] = i; i = ti;
        }
    }
}

__device__ __forceinline__ void head5(const float v[5], const int ix[5], int ptr,
                                      float& hv, int& hi) {
    hv = NEGINF; hi = 0x7fffffff;
    if (ptr == 0)      { hv = v[0]; hi = ix[0]; }
    else if (ptr == 1) { hv = v[1]; hi = ix[1]; }
    else if (ptr == 2) { hv = v[2]; hi = ix[2]; }
    else if (ptr == 3) { hv = v[3]; hi = ix[3]; }
    else if (ptr == 4) { hv = v[4]; hi = ix[4]; }
}

__global__ void __launch_bounds__(256) k_topk(const float* __restrict__ outA,
                                              const float* __restrict__ mask,
                                              float* __restrict__ outM) {
    const int lane = threadIdx.x & 31;
    const int g = blockIdx.x * 8 + (threadIdx.x >> 5);   // global row id
    const float4* Ar = (const float4*)(outA + (size_t)g * NN);

    // phase 1: batch load (8 independent LDG.128 in flight)
    float4 t[8];
#pragma unroll
    for (int k = 0; k < 8; k++) t[k] = Ar[k * 32 + lane];

    // phase 2: rare-branch scan
    float v[5]; int ix[5];
#pragma unroll
    for (int p = 0; p < 5; p++) { v[p] = NEGINF; ix[p] = 0x7fffffff; }
    float vmin = NEGINF;
#pragma unroll
    for (int k = 0; k < 8; k++) {
        float m = fmaxf(fmaxf(t[k].x, t[k].y), fmaxf(t[k].z, t[k].w));
        if (m > vmin) {
            const int cb = (k * 32 + lane) * 4;
            ins5(t[k].x, cb, v, ix);
            ins5(t[k].y, cb + 1, v, ix);
            ins5(t[k].z, cb + 2, v, ix);
            ins5(t[k].w, cb + 3, v, ix);
            vmin = v[4];
        }
    }

    // 32-lane merge: 5 rounds, lower index wins ties
    int wout[5];
    int ptr = 0;
#pragma unroll
    for (int t5 = 0; t5 < 5; t5++) {
        float hv; int hi;
        head5(v, ix, ptr, hv, hi);
        const float mv = hv; const int mi_ = hi;
#pragma unroll
        for (int off = 1; off <= 16; off <<= 1) {
            float ov = __shfl_xor_sync(0xffffffffu, hv, off);
            int   oi = __shfl_xor_sync(0xffffffffu, hi, off);
            if (ov > hv || (ov == hv && oi < hi)) { hv = ov; hi = oi; }
        }
        wout[t5] = hi;
        if (mv == hv && mi_ == hi) ptr++;
    }

    // gather top-5 mask rows + max (original f32 mask; L2-resident)
    const int bc = g >> 10;   // b*C1 + c
    const float* mkb = mask + (size_t)bc * (NN * DD);
    float m0 = NEGINF, m1 = NEGINF;
#pragma unroll
    for (int p = 0; p < 5; p++) {
        const float* mr = mkb + (size_t)wout[p] * DD;
        m0 = fmaxf(m0, mr[lane]);
        m1 = fmaxf(m1, mr[lane + 32]);
    }
    outM[(size_t)g * DD + lane]      = m0;
    outM[(size_t)g * DD + lane + 32] = m1;
}

// ---------------------------------------------------------------------------
extern "C" void kernel_launch(void* const* d_in, const int* in_sizes, int n_in,
                              void* d_out, int out_size) {
    (void)in_sizes; (void)n_in; (void)out_size;
    const float* x    = (const float*)d_in[0];
    const float* A    = (const float*)d_in[1];
    const float* mask = (const float*)d_in[2];
    float* outA = (float*)d_out;
    float* outM = outA + (size_t)BB * C1 * NN * NN;

    cudaFuncSetAttribute(k_S3, cudaFuncAttributeMaxDynamicSharedMemorySize, KS3_SMEM);
    cudaFuncSetAttribute(k_mm, cudaFuncAttributeMaxDynamicSharedMemorySize, KMM_SMEM);

    k_conv<<<(NX4 + NM4 + 255) / 256, 256>>>(x, mask);
    k_S3<<<dim3(16, 8, BB), 256, KS3_SMEM>>>();
    k_sreduce2<<<BB * NN * NN / 4 / 256, 256>>>(A);
    k_mm<<<dim3(8, C1, BB), 256, KMM_SMEM>>>(outA);
    k_topk<<<BB * C1 * NN / 8, 256>>>(outA, mask, outM);
}

// round 10
// speedup vs baseline: 1.2157x; 1.2157x over previous
#include <cuda_runtime.h>
#include <cuda_bf16.h>

// Problem constants
#define BB  4
#define CX  16
#define CA  8
#define C1  16
#define NN  1024
#define DD  64
#define NEGINF (-3.402823466e38f)

// 0.02*sigmoid(z) = 0.01 + 0.01*tanh(z/2); z = S*mm/sqrt(10)
// -> store S' = S * 0.5/sqrt(10), A' = Amean + 0.01; out = fma(0.01, tanh(S'*mm), A')
#define SSCALE 0.15811388300841898f

// Scratch (static __device__ arrays; no dynamic allocation)
__device__ __align__(16) __nv_bfloat16 g_Sp[8u * BB * NN * NN];    // 67 MB partial S (bf16)
__device__ __align__(16) float g_SA[2u * BB * NN * NN];            // 33.6 MB (S',A') interleaved
__device__ __align__(16) __nv_bfloat16 g_xbf[BB * CX * NN * DD];   // 8.4 MB
__device__ __align__(16) __nv_bfloat16 g_mbf[BB * C1 * NN * DD];   // 8.4 MB

// ---------------------------------------------------------------------------
// PTX helpers
// ---------------------------------------------------------------------------
__device__ __forceinline__ unsigned sptr(const void* p) {
    return (unsigned)__cvta_generic_to_shared(p);
}

__device__ __forceinline__ void ldsm4(unsigned a[4], unsigned addr) {
    asm volatile("ldmatrix.sync.aligned.m8n8.x4.shared.b16 {%0,%1,%2,%3}, [%4];"
                 : "=r"(a[0]), "=r"(a[1]), "=r"(a[2]), "=r"(a[3]) : "r"(addr));
}

__device__ __forceinline__ void mma16816(float c[4], const unsigned a[4],
                                         unsigned b0, unsigned b1) {
    asm volatile(
        "mma.sync.aligned.m16n8k16.row.col.f32.bf16.bf16.f32 "
        "{%0,%1,%2,%3}, {%4,%5,%6,%7}, {%8,%9}, {%0,%1,%2,%3};"
        : "+f"(c[0]), "+f"(c[1]), "+f"(c[2]), "+f"(c[3])
        : "r"(a[0]), "r"(a[1]), "r"(a[2]), "r"(a[3]), "r"(b0), "r"(b1));
}

__device__ __forceinline__ void cpasync16(unsigned dst, const void* src) {
    asm volatile("cp.async.cg.shared.global [%0], [%1], 16;" :: "r"(dst), "l"(src));
}
#define CP_COMMIT() asm volatile("cp.async.commit_group;")
#define CP_WAIT1()  asm volatile("cp.async.wait_group 1;")
#define CP_WAIT0()  asm volatile("cp.async.wait_group 0;")

__device__ __forceinline__ float tanhap(float x) {
    float r;
    asm("tanh.approx.f32 %0, %1;" : "=f"(r) : "f"(x));
    return r;
}

__device__ __forceinline__ unsigned packbf2(float a, float b) {
    __nv_bfloat162 h = __floats2bfloat162_rn(a, b);
    return *reinterpret_cast<unsigned*>(&h);
}

// float -> order-preserving uint
__device__ __forceinline__ unsigned ordf(float f) {
    unsigned u = __float_as_uint(f);
    return (u & 0x80000000u) ? ~u : (u | 0x80000000u);
}

// ---------------------------------------------------------------------------
// Swizzled bf16 tiles: [rows][64] bf16, 128B/row; 16B chunk' = chunk ^ (row&7)
// ---------------------------------------------------------------------------
__device__ __forceinline__ void pf_tile128(const __nv_bfloat16* src,
                                           __nv_bfloat16* dst, int tid) {
#pragma unroll
    for (int q = 0; q < 4; q++) {
        int id = tid + q * 256;
        int r = id >> 3, cc = id & 7;
        cpasync16(sptr(dst + r * 64 + ((cc ^ (r & 7)) << 3)), src + r * 64 + cc * 8);
    }
}

__device__ __forceinline__ void pf_tile64(const __nv_bfloat16* src,
                                          __nv_bfloat16* dst, int tid) {
#pragma unroll
    for (int q = 0; q < 2; q++) {
        int id = tid + q * 256;
        int r = id >> 3, cc = id & 7;
        cpasync16(sptr(dst + r * 64 + ((cc ^ (r & 7)) << 3)), src + r * 64 + cc * 8);
    }
}

// SA subtile prefetch: 128 rows x 128 bytes (16 col-pairs) into smem stride 128
__device__ __forceinline__ void pf_sa(const float* src, char* dst, int tid) {
#pragma unroll
    for (int q = 0; q < 4; q++) {
        int id = tid + q * 256;
        int r = id >> 3, c = id & 7;
        cpasync16(sptr(dst + r * 128 + c * 16),
                  (const char*)src + (size_t)r * 8192 + c * 16);
    }
}

// A fragments for a 16-row slice, cached in regs
__device__ __forceinline__ void load_afrag(const __nv_bfloat16* xi16, int lane,
                                           unsigned a[4][4]) {
    const int ar = (lane & 7) + (((lane >> 3) & 1) << 3);
    const int ak8 = lane >> 4;
#pragma unroll
    for (int ks = 0; ks < 4; ks++)
        ldsm4(a[ks], sptr(xi16 + ar * 64 + (((2 * ks + ak8) ^ (ar & 7)) << 3)));
}

// acc[8] += A(16x64) * B(rows n0..n0+15 of 64x64 tile)^T
__device__ __forceinline__ void subtile_mma(const __nv_bfloat16* bt, int n0, int lane,
                                            const unsigned a[4][4], float acc[8]) {
    const int m = lane >> 3;
    const int br = n0 + (lane & 7) + ((m >> 1) << 3);
    const int bk8 = m & 1;
#pragma unroll
    for (int ks = 0; ks < 4; ks++) {
        unsigned b[4];
        ldsm4(b, sptr(bt + br * 64 + (((2 * ks + bk8) ^ (br & 7)) << 3)));
        mma16816(acc, a[ks], b[0], b[1]);
        mma16816(acc + 4, a[ks], b[2], b[3]);
    }
}

// ---------------------------------------------------------------------------
// Prep: bf16 conversion of x and mask in one kernel
// ---------------------------------------------------------------------------
#define NX4 (BB * CX * NN * DD / 4)
#define NM4 (BB * C1 * NN * DD / 4)
__global__ void k_conv(const float* __restrict__ x, const float* __restrict__ mask) {
    int idx = blockIdx.x * blockDim.x + threadIdx.x;
    const float4* src;
    uint2* dst;
    int i;
    if (idx < NX4) { src = (const float4*)x; dst = (uint2*)g_xbf; i = idx; }
    else if (idx < NX4 + NM4) { src = (const float4*)mask; dst = (uint2*)g_mbf; i = idx - NX4; }
    else return;
    float4 v = src[i];
    uint2 u;
    u.x = packbf2(v.x, v.y);
    u.y = packbf2(v.z, v.w);
    dst[i] = u;
}

// ---------------------------------------------------------------------------
// k_S3: partial S for 2 channels, 64-row tiles. grid (16, 8, 4), 256 thr.
// ---------------------------------------------------------------------------
#define KS3_SMEM (2*64*64*2 + 2*2*64*64*2 + 2*64*4 + 2*64*2*4 + 2*64*4)

__global__ void __launch_bounds__(256, 3) k_S3() {
    extern __shared__ char sm[];
    __nv_bfloat16* xi  = (__nv_bfloat16*)sm;            // [2ch][64*64]
    __nv_bfloat16* xjb = xi + 2 * 64 * 64;              // [2buf][2ch][64*64]
    float* P  = (float*)(xjb + 2 * 2 * 64 * 64);        // [2][64]
    float* Zw = P + 2 * 64;                             // [2][64][2]
    float* Zi = Zw + 2 * 64 * 2;                        // [2][64]

    const int tid = threadIdx.x, lane = tid & 31, w = tid >> 5;
    const int wr = w & 3, wc = w >> 2;
    const int itile = blockIdx.x, cg = blockIdx.y, b = blockIdx.z;

    const __nv_bfloat16* xc0 = g_xbf + (size_t)(b * CX + cg * 2) * NN * DD;
    const __nv_bfloat16* xc1 = xc0 + NN * DD;

    pf_tile64(xc0 + itile * 64 * 64, xi, tid);
    pf_tile64(xc1 + itile * 64 * 64, xi + 64 * 64, tid);
    CP_COMMIT();
    pf_tile64(xc0, xjb, tid);
    pf_tile64(xc1, xjb + 64 * 64, tid);
    CP_COMMIT();
    CP_WAIT1();
    __syncthreads();

    // P = ||row||^2 from bf16 values
    if (tid < 128) {
        int c = tid >> 6, r = tid & 63;
        const __nv_bfloat16* row = xi + c * 4096 + r * 64;
        float s = 0.f;
#pragma unroll
        for (int cc = 0; cc < 8; cc++) {
            const __nv_bfloat16* ch = row + ((cc ^ (r & 7)) << 3);
#pragma unroll
            for (int e = 0; e < 8; e++) {
                float v = __bfloat162float(ch[e]);
                s += v * v;
            }
        }
        P[c * 64 + r] = s;
    }
    __syncthreads();

    unsigned a0[4][4], a1[4][4];
    load_afrag(xi + wr * 16 * 64, lane, a0);
    load_afrag(xi + 4096 + wr * 16 * 64, lane, a1);

    const int lr0 = wr * 16 + (lane >> 2), lr1 = lr0 + 8;
    const float p00 = P[lr0], p01 = P[lr1], p10 = P[64 + lr0], p11 = P[64 + lr1];

    // ---- Pass Z ----
    float z00 = 0.f, z01 = 0.f, z10 = 0.f, z11 = 0.f;
    for (int jt = 0; jt < 16; jt++) {
        if (jt < 15) {
            __nv_bfloat16* nb = xjb + ((jt + 1) & 1) * 8192;
            pf_tile64(xc0 + (jt + 1) * 64 * 64, nb, tid);
            pf_tile64(xc1 + (jt + 1) * 64 * 64, nb + 4096, tid);
            CP_COMMIT(); CP_WAIT1();
        } else CP_WAIT0();
        __syncthreads();
        const __nv_bfloat16* bt = xjb + (jt & 1) * 8192;
#pragma unroll
        for (int nn = 0; nn < 2; nn++) {
            const int n0 = (wc * 2 + nn) * 16;
            {
                float acc[8] = {0.f, 0.f, 0.f, 0.f, 0.f, 0.f, 0.f, 0.f};
                subtile_mma(bt, n0, lane, a0, acc);
                z00 += __expf(acc[0] - p00) + __expf(acc[1] - p00)
                     + __expf(acc[4] - p00) + __expf(acc[5] - p00);
                z01 += __expf(acc[2] - p01) + __expf(acc[3] - p01)
                     + __expf(acc[6] - p01) + __expf(acc[7] - p01);
            }
            {
                float acc[8] = {0.f, 0.f, 0.f, 0.f, 0.f, 0.f, 0.f, 0.f};
                subtile_mma(bt + 4096, n0, lane, a1, acc);
                z10 += __expf(acc[0] - p10) + __expf(acc[1] - p10)
                     + __expf(acc[4] - p10) + __expf(acc[5] - p10);
                z11 += __expf(acc[2] - p11) + __expf(acc[3] - p11)
                     + __expf(acc[6] - p11) + __expf(acc[7] - p11);
            }
        }
        __syncthreads();
    }
    z00 += __shfl_xor_sync(0xffffffffu, z00, 1); z00 += __shfl_xor_sync(0xffffffffu, z00, 2);
    z01 += __shfl_xor_sync(0xffffffffu, z01, 1); z01 += __shfl_xor_sync(0xffffffffu, z01, 2);
    z10 += __shfl_xor_sync(0xffffffffu, z10, 1); z10 += __shfl_xor_sync(0xffffffffu, z10, 2);
    z11 += __shfl_xor_sync(0xffffffffu, z11, 1); z11 += __shfl_xor_sync(0xffffffffu, z11, 2);
    if ((lane & 3) == 0) {
        Zw[lr0 * 2 + wc]       = z00;
        Zw[lr1 * 2 + wc]       = z01;
        Zw[128 + lr0 * 2 + wc] = z10;
        Zw[128 + lr1 * 2 + wc] = z11;
    }
    __syncthreads();
    if (tid < 128) {
        int c = tid >> 6, r = tid & 63;
        Zi[c * 64 + r] = 1.f / (16.f * (Zw[c * 128 + r * 2] + Zw[c * 128 + r * 2 + 1]));
    }
    pf_tile64(xc0, xjb, tid);
    pf_tile64(xc1, xjb + 4096, tid);
    CP_COMMIT();
    __syncthreads();

    const float zi00 = Zi[lr0], zi01 = Zi[lr1];
    const float zi10 = Zi[64 + lr0], zi11 = Zi[64 + lr1];

    __nv_bfloat16* spBase = g_Sp + (size_t)(cg * BB + b) * NN * NN + (size_t)(itile * 64) * NN;

    for (int jt = 0; jt < 16; jt++) {
        if (jt < 15) {
            __nv_bfloat16* nb = xjb + ((jt + 1) & 1) * 8192;
            pf_tile64(xc0 + (jt + 1) * 64 * 64, nb, tid);
            pf_tile64(xc1 + (jt + 1) * 64 * 64, nb + 4096, tid);
            CP_COMMIT(); CP_WAIT1();
        } else CP_WAIT0();
        __syncthreads();
        const __nv_bfloat16* bt = xjb + (jt & 1) * 8192;

#pragma unroll
        for (int nn = 0; nn < 2; nn++) {
            const int n = wc * 2 + nn;
            float Sa[8];
#pragma unroll
            for (int k = 0; k < 8; k++) Sa[k] = 0.f;
            {
                float acc[8] = {0.f, 0.f, 0.f, 0.f, 0.f, 0.f, 0.f, 0.f};
                subtile_mma(bt, n * 16, lane, a0, acc);
                Sa[0] += __expf(acc[0] - p00) * zi00;
                Sa[1] += __expf(acc[1] - p00) * zi00;
                Sa[4] += __expf(acc[4] - p00) * zi00;
                Sa[5] += __expf(acc[5] - p00) * zi00;
                Sa[2] += __expf(acc[2] - p01) * zi01;
                Sa[3] += __expf(acc[3] - p01) * zi01;
                Sa[6] += __expf(acc[6] - p01) * zi01;
                Sa[7] += __expf(acc[7] - p01) * zi01;
            }
            {
                float acc[8] = {0.f, 0.f, 0.f, 0.f, 0.f, 0.f, 0.f, 0.f};
                subtile_mma(bt + 4096, n * 16, lane, a1, acc);
                Sa[0] += __expf(acc[0] - p10) * zi10;
                Sa[1] += __expf(acc[1] - p10) * zi10;
                Sa[4] += __expf(acc[4] - p10) * zi10;
                Sa[5] += __expf(acc[5] - p10) * zi10;
                Sa[2] += __expf(acc[2] - p11) * zi11;
                Sa[3] += __expf(acc[3] - p11) * zi11;
                Sa[6] += __expf(acc[6] - p11) * zi11;
                Sa[7] += __expf(acc[7] - p11) * zi11;
            }
            const int cb = jt * 64 + n * 16 + 2 * (lane & 3);
            *(unsigned*)(spBase + (size_t)lr0 * NN + cb)     = packbf2(Sa[0], Sa[1]);
            *(unsigned*)(spBase + (size_t)lr0 * NN + cb + 8) = packbf2(Sa[4], Sa[5]);
            *(unsigned*)(spBase + (size_t)lr1 * NN + cb)     = packbf2(Sa[2], Sa[3]);
            *(unsigned*)(spBase + (size_t)lr1 * NN + cb + 8) = packbf2(Sa[6], Sa[7]);
        }
        __syncthreads();
    }
}

// ---------------------------------------------------------------------------
// k_sreduce2: sum 8 bf16 partial S slices + mean of A over CA, write
// interleaved (S*SSCALE, Amean+0.01) pairs.
// ---------------------------------------------------------------------------
__global__ void k_sreduce2(const float* __restrict__ A) {
    int i = blockIdx.x * 256 + threadIdx.x;   // group of 4 elements
    const int per_b = NN * NN / 4;
    int b = i / per_b;
    int r = i - b * per_b;

    const uint2* sp = (const uint2*)g_Sp;
    float4 s = make_float4(0.f, 0.f, 0.f, 0.f);
#pragma unroll
    for (int g = 0; g < 8; g++) {
        uint2 u = sp[(size_t)(g * BB + b) * per_b + r];
        __nv_bfloat162 h0 = *reinterpret_cast<__nv_bfloat162*>(&u.x);
        __nv_bfloat162 h1 = *reinterpret_cast<__nv_bfloat162*>(&u.y);
        float2 f0 = __bfloat1622float2(h0);
        float2 f1 = __bfloat1622float2(h1);
        s.x += f0.x; s.y += f0.y; s.z += f1.x; s.w += f1.y;
    }
    const float4* ap = (const float4*)A + (size_t)b * CA * per_b + r;
    float4 a = ap[0];
#pragma unroll
    for (int ch = 1; ch < CA; ch++) {
        float4 v = ap[(size_t)ch * per_b];
        a.x += v.x; a.y += v.y; a.z += v.z; a.w += v.w;
    }
    float4 o1, o2;
    o1.x = s.x * SSCALE; o1.y = a.x * 0.125f + 0.01f;
    o1.z = s.y * SSCALE; o1.w = a.y * 0.125f + 0.01f;
    o2.x = s.z * SSCALE; o2.y = a.z * 0.125f + 0.01f;
    o2.z = s.w * SSCALE; o2.w = a.w * 0.125f + 0.01f;
    float4* out = (float4*)g_SA + (size_t)i * 2;
    out[0] = o1;
    out[1] = o2;
}

// ---------------------------------------------------------------------------
// k_mm2: per (itile, cpair, b): 2 channels share a cp.async-pipelined SA
// stream through smem. grid (8, 8, 4) = 256 blocks, 2 blocks/SM.
// SA subtile pipeline: 3 smem stages, prefetch distance 2, wait_group 1,
// one barrier per subtile.
// smem: mi0 16K | mi1 16K | mjb[2buf][2ch] 32K | sab[3] 48K = 112KB
// ---------------------------------------------------------------------------
#define KMM2_SMEM (2*128*64*2 + 2*2*64*64*2 + 3*128*128)

__global__ void __launch_bounds__(256, 2) k_mm2(float* __restrict__ outA) {
    extern __shared__ char sm[];
    __nv_bfloat16* mi0 = (__nv_bfloat16*)sm;               // [128*64]
    __nv_bfloat16* mi1 = mi0 + 128 * 64;                   // [128*64]
    char* mjb = sm + 32768;                                // [2buf][2ch][8192B]
    char* sab = sm + 65536;                                // [3][128*128B]

    const int tid = threadIdx.x, lane = tid & 31, w = tid >> 5;
    const int itile = blockIdx.x, cpair = blockIdx.y, b = blockIdx.z;
    const int c0 = cpair * 2;

    const __nv_bfloat16* mc0 = g_mbf + (size_t)(b * C1 + c0) * NN * DD;
    const __nv_bfloat16* mc1 = mc0 + NN * DD;
    const float* saBase = g_SA + (size_t)(b * NN + itile * 128) * (NN * 2);

    // prime: G0 = {mi tiles, mjb buf0 both ch, SA(0)}, G1 = {SA(1)}
    pf_tile128(mc0 + itile * 128 * 64, mi0, tid);
    pf_tile128(mc1 + itile * 128 * 64, mi1, tid);
    pf_tile64(mc0, (__nv_bfloat16*)(mjb), tid);
    pf_tile64(mc1, (__nv_bfloat16*)(mjb + 8192), tid);
    pf_sa(saBase, sab, tid);
    CP_COMMIT();
    pf_sa(saBase + 32, sab + 16384, tid);
    CP_COMMIT();

    CP_WAIT1();
    __syncthreads();

    unsigned a0[4][4], a1[4][4];
    load_afrag(mi0 + w * 16 * 64, lane, a0);
    load_afrag(mi1 + w * 16 * 64, lane, a1);

    const int lr0 = w * 16 + (lane >> 2), lr1 = lr0 + 8;
    const int gr0 = itile * 128 + lr0, gr1 = itile * 128 + lr1;
    float* O00 = outA + ((size_t)(b * C1 + c0) * NN + gr0) * NN;
    float* O01 = outA + ((size_t)(b * C1 + c0) * NN + gr1) * NN;
    float* O10 = O00 + (size_t)NN * NN;
    float* O11 = O01 + (size_t)NN * NN;

    const int lq = 2 * (lane & 3);
    const int saoff0 = lr0 * 128 + (lane & 3) * 16;
    const int saoff1 = lr1 * 128 + (lane & 3) * 16;

    int sidx = 0;          // sab stage of current subtile
    int pidx = 2;          // sab stage for prefetch (k+2)

    for (int k = 0; k < 64; k++) {
        const int jt = k >> 2, n = k & 3;

        CP_WAIT1();
        __syncthreads();

        // prefetch SA(k+2) + next mask tiles (after barrier: safe buffer reuse)
        if (k < 62) {
            pf_sa(saBase + (k + 2) * 32, sab + pidx * 16384, tid);
            if (n == 0 && jt < 15) {
                char* nb = mjb + ((jt + 1) & 1) * 16384;
                pf_tile64(mc0 + (jt + 1) * 4096, (__nv_bfloat16*)nb, tid);
                pf_tile64(mc1 + (jt + 1) * 4096, (__nv_bfloat16*)(nb + 8192), tid);
            }
        }
        CP_COMMIT();

        // SA from smem
        const char* sap = sab + sidx * 16384;
        const float4 q0 = *(const float4*)(sap + saoff0);
        const float4 q1 = *(const float4*)(sap + saoff0 + 64);
        const float4 q2 = *(const float4*)(sap + saoff1);
        const float4 q3 = *(const float4*)(sap + saoff1 + 64);

        const __nv_bfloat16* bt0 = (const __nv_bfloat16*)(mjb + (jt & 1) * 16384);
        const __nv_bfloat16* bt1 = (const __nv_bfloat16*)(mjb + (jt & 1) * 16384 + 8192);
        const int cb = jt * 64 + n * 16 + lq;

        // channel 0
        {
            float acc[8] = {0.f, 0.f, 0.f, 0.f, 0.f, 0.f, 0.f, 0.f};
            subtile_mma(bt0, n * 16, lane, a0, acc);
            float o0 = fmaf(0.01f, tanhap(q0.x * acc[0]), q0.y);
            float o1 = fmaf(0.01f, tanhap(q0.z * acc[1]), q0.w);
            float o4 = fmaf(0.01f, tanhap(q1.x * acc[4]), q1.y);
            float o5 = fmaf(0.01f, tanhap(q1.z * acc[5]), q1.w);
            float o2 = fmaf(0.01f, tanhap(q2.x * acc[2]), q2.y);
            float o3 = fmaf(0.01f, tanhap(q2.z * acc[3]), q2.w);
            float o6 = fmaf(0.01f, tanhap(q3.x * acc[6]), q3.y);
            float o7 = fmaf(0.01f, tanhap(q3.z * acc[7]), q3.w);
            *(float2*)(O00 + cb)     = make_float2(o0, o1);
            *(float2*)(O00 + cb + 8) = make_float2(o4, o5);
            *(float2*)(O01 + cb)     = make_float2(o2, o3);
            *(float2*)(O01 + cb + 8) = make_float2(o6, o7);
        }
        // channel 1
        {
            float acc[8] = {0.f, 0.f, 0.f, 0.f, 0.f, 0.f, 0.f, 0.f};
            subtile_mma(bt1, n * 16, lane, a1, acc);
            float o0 = fmaf(0.01f, tanhap(q0.x * acc[0]), q0.y);
            float o1 = fmaf(0.01f, tanhap(q0.z * acc[1]), q0.w);
            float o4 = fmaf(0.01f, tanhap(q1.x * acc[4]), q1.y);
            float o5 = fmaf(0.01f, tanhap(q1.z * acc[5]), q1.w);
            float o2 = fmaf(0.01f, tanhap(q2.x * acc[2]), q2.y);
            float o3 = fmaf(0.01f, tanhap(q2.z * acc[3]), q2.w);
            float o6 = fmaf(0.01f, tanhap(q3.x * acc[6]), q3.y);
            float o7 = fmaf(0.01f, tanhap(q3.z * acc[7]), q3.w);
            *(float2*)(O10 + cb)     = make_float2(o0, o1);
            *(float2*)(O10 + cb + 8) = make_float2(o4, o5);
            *(float2*)(O11 + cb)     = make_float2(o2, o3);
            *(float2*)(O11 + cb + 8) = make_float2(o6, o7);
        }

        sidx = (sidx == 2) ? 0 : sidx + 1;
        pidx = (pidx == 2) ? 0 : pidx + 1;
    }
}

// ---------------------------------------------------------------------------
// k_topk: warp per row. Batch-load row (MLP=8), rare-branch top-5, REDUX
// merge (float-as-ordered-uint), gather mask rows + max.
// ---------------------------------------------------------------------------
__device__ __forceinline__ void ins5(float x, int i, float v[5], int ix[5]) {
#pragma unroll
    for (int p = 0; p < 5; p++) {
        if (x > v[p]) {
            float tv = v[p]; v[p] = x; x = tv;
            int ti = ix[p]; ix[p] = i; i = ti;
        }
    }
}

__device__ __forceinline__ void head5(const float v[5], const int ix[5], int ptr,
                                      float& hv, int& hi) {
    hv = NEGINF; hi = 0x7fffffff;
    if (ptr == 0)      { hv = v[0]; hi = ix[0]; }
    else if (ptr == 1) { hv = v[1]; hi = ix[1]; }
    else if (ptr == 2) { hv = v[2]; hi = ix[2]; }
    else if (ptr == 3) { hv = v[3]; hi = ix[3]; }
    else if (ptr == 4) { hv = v[4]; hi = ix[4]; }
}

__global__ void __launch_bounds__(256) k_topk(const float* __restrict__ outA,
                                              const float* __restrict__ mask,
                                              float* __restrict__ outM) {
    const int lane = threadIdx.x & 31;
    const int g = blockIdx.x * 8 + (threadIdx.x >> 5);   // global row id
    const float4* Ar = (const float4*)(outA + (size_t)g * NN);

    // phase 1: batch load (8 independent LDG.128 in flight)
    float4 t[8];
#pragma unroll
    for (int k = 0; k < 8; k++) t[k] = Ar[k * 32 + lane];

    // phase 2: rare-branch scan
    float v[5]; int ix[5];
#pragma unroll
    for (int p = 0; p < 5; p++) { v[p] = NEGINF; ix[p] = 0x7fffffff; }
    float vmin = NEGINF;
#pragma unroll
    for (int k = 0; k < 8; k++) {
        float m = fmaxf(fmaxf(t[k].x, t[k].y), fmaxf(t[k].z, t[k].w));
        if (m > vmin) {
            const int cb = (k * 32 + lane) * 4;
            ins5(t[k].x, cb, v, ix);
            ins5(t[k].y, cb + 1, v, ix);
            ins5(t[k].z, cb + 2, v, ix);
            ins5(t[k].w, cb + 3, v, ix);
            vmin = v[4];
        }
    }

    // REDUX merge: 5 rounds of warp-max on order-preserving uint keys
    int wout[5];
    int ptr = 0;
#pragma unroll
    for (int t5 = 0; t5 < 5; t5++) {
        float hv; int hi;
        head5(v, ix, ptr, hv, hi);
        unsigned key = ordf(hv);
        unsigned mx = __reduce_max_sync(0xffffffffu, key);
        unsigned ball = __ballot_sync(0xffffffffu, key == mx);
        int src = __ffs((int)ball) - 1;
        wout[t5] = __shfl_sync(0xffffffffu, hi, src);
        if (lane == src) ptr++;
    }

    // gather top-5 mask rows + max (original f32 mask; L2-resident)
    const int bc = g >> 10;   // b*C1 + c
    const float* mkb = mask + (size_t)bc * (NN * DD);
    float m0 = NEGINF, m1 = NEGINF;
#pragma unroll
    for (int p = 0; p < 5; p++) {
        const float* mr = mkb + (size_t)wout[p] * DD;
        m0 = fmaxf(m0, mr[lane]);
        m1 = fmaxf(m1, mr[lane + 32]);
    }
    outM[(size_t)g * DD + lane]      = m0;
    outM[(size_t)g * DD + lane + 32] = m1;
}

// ---------------------------------------------------------------------------
extern "C" void kernel_launch(void* const* d_in, const int* in_sizes, int n_in,
                              void* d_out, int out_size) {
    (void)in_sizes; (void)n_in; (void)out_size;
    const float* x    = (const float*)d_in[0];
    const float* A    = (const float*)d_in[1];
    const float* mask = (const float*)d_in[2];
    float* outA = (float*)d_out;
    float* outM = outA + (size_t)BB * C1 * NN * NN;

    cudaFuncSetAttribute(k_S3, cudaFuncAttributeMaxDynamicSharedMemorySize, KS3_SMEM);
    cudaFuncSetAttribute(k_mm2, cudaFuncAttributeMaxDynamicSharedMemorySize, KMM2_SMEM);

    k_conv<<<(NX4 + NM4 + 255) / 256, 256>>>(x, mask);
    k_S3<<<dim3(16, 8, BB), 256, KS3_SMEM>>>();
    k_sreduce2<<<BB * NN * NN / 4 / 256, 256>>>(A);
    k_mm2<<<dim3(8, 8, BB), 256, KMM2_SMEM>>>(outA);
    k_topk<<<BB * C1 * NN / 8, 256>>>(outA, mask, outM);
}

// round 11
// speedup vs baseline: 1.2585x; 1.0352x over previous
#include <cuda_runtime.h>
#include <cuda_bf16.h>

// Problem constants
#define BB  4
#define CX  16
#define CA  8
#define C1  16
#define NN  1024
#define DD  64
#define NEGINF (-3.402823466e38f)

// 0.02*sigmoid(z) = 0.01 + 0.01*tanh(z/2); z = S*mm/sqrt(10)
// -> store S' = S * 0.5/sqrt(10), A' = Amean + 0.01; out = fma(0.01, tanh(S'*mm), A')
#define SSCALE 0.15811388300841898f

// Scratch (static __device__ arrays; no dynamic allocation)
__device__ __align__(16) __nv_bfloat16 g_Sp[16u * BB * NN * NN];   // 134 MB per-channel exp (bf16)
__device__ __align__(16) float g_Zi[BB * CX * NN];                 // 256 KB per-(b,ch,row) 1/(16Z)
__device__ __align__(16) float g_SA[2u * BB * NN * NN];            // 33.6 MB (S',A') interleaved
__device__ __align__(16) __nv_bfloat16 g_xbf[BB * CX * NN * DD];   // 8.4 MB
__device__ __align__(16) __nv_bfloat16 g_mbf[BB * C1 * NN * DD];   // 8.4 MB

// ---------------------------------------------------------------------------
// PTX helpers
// ---------------------------------------------------------------------------
__device__ __forceinline__ unsigned sptr(const void* p) {
    return (unsigned)__cvta_generic_to_shared(p);
}

__device__ __forceinline__ void ldsm4(unsigned a[4], unsigned addr) {
    asm volatile("ldmatrix.sync.aligned.m8n8.x4.shared.b16 {%0,%1,%2,%3}, [%4];"
                 : "=r"(a[0]), "=r"(a[1]), "=r"(a[2]), "=r"(a[3]) : "r"(addr));
}

__device__ __forceinline__ void mma16816(float c[4], const unsigned a[4],
                                         unsigned b0, unsigned b1) {
    asm volatile(
        "mma.sync.aligned.m16n8k16.row.col.f32.bf16.bf16.f32 "
        "{%0,%1,%2,%3}, {%4,%5,%6,%7}, {%8,%9}, {%0,%1,%2,%3};"
        : "+f"(c[0]), "+f"(c[1]), "+f"(c[2]), "+f"(c[3])
        : "r"(a[0]), "r"(a[1]), "r"(a[2]), "r"(a[3]), "r"(b0), "r"(b1));
}

__device__ __forceinline__ void cpasync16(unsigned dst, const void* src) {
    asm volatile("cp.async.cg.shared.global [%0], [%1], 16;" :: "r"(dst), "l"(src));
}
#define CP_COMMIT() asm volatile("cp.async.commit_group;")
#define CP_WAIT1()  asm volatile("cp.async.wait_group 1;")
#define CP_WAIT0()  asm volatile("cp.async.wait_group 0;")

__device__ __forceinline__ float tanhap(float x) {
    float r;
    asm("tanh.approx.f32 %0, %1;" : "=f"(r) : "f"(x));
    return r;
}

__device__ __forceinline__ unsigned packbf2(float a, float b) {
    __nv_bfloat162 h = __floats2bfloat162_rn(a, b);
    return *reinterpret_cast<unsigned*>(&h);
}

// float -> order-preserving uint
__device__ __forceinline__ unsigned ordf(float f) {
    unsigned u = __float_as_uint(f);
    return (u & 0x80000000u) ? ~u : (u | 0x80000000u);
}

// ---------------------------------------------------------------------------
// Swizzled bf16 tiles: [rows][64] bf16, 128B/row; 16B chunk' = chunk ^ (row&7)
// ---------------------------------------------------------------------------
__device__ __forceinline__ void pf_tile128(const __nv_bfloat16* src,
                                           __nv_bfloat16* dst, int tid) {
#pragma unroll
    for (int q = 0; q < 4; q++) {
        int id = tid + q * 256;
        int r = id >> 3, cc = id & 7;
        cpasync16(sptr(dst + r * 64 + ((cc ^ (r & 7)) << 3)), src + r * 64 + cc * 8);
    }
}

__device__ __forceinline__ void pf_tile64(const __nv_bfloat16* src,
                                          __nv_bfloat16* dst, int tid) {
#pragma unroll
    for (int q = 0; q < 2; q++) {
        int id = tid + q * 256;
        int r = id >> 3, cc = id & 7;
        cpasync16(sptr(dst + r * 64 + ((cc ^ (r & 7)) << 3)), src + r * 64 + cc * 8);
    }
}

// SA subtile prefetch: 128 rows x 128 bytes into smem stride 128
__device__ __forceinline__ void pf_sa(const float* src, char* dst, int tid) {
#pragma unroll
    for (int q = 0; q < 4; q++) {
        int id = tid + q * 256;
        int r = id >> 3, c = id & 7;
        cpasync16(sptr(dst + r * 128 + c * 16),
                  (const char*)src + (size_t)r * 8192 + c * 16);
    }
}

// A fragments for a 16-row slice, cached in regs
__device__ __forceinline__ void load_afrag(const __nv_bfloat16* xi16, int lane,
                                           unsigned a[4][4]) {
    const int ar = (lane & 7) + (((lane >> 3) & 1) << 3);
    const int ak8 = lane >> 4;
#pragma unroll
    for (int ks = 0; ks < 4; ks++)
        ldsm4(a[ks], sptr(xi16 + ar * 64 + (((2 * ks + ak8) ^ (ar & 7)) << 3)));
}

// acc[8] += A(16x64) * B(rows n0..n0+15 of 64x64 tile)^T
__device__ __forceinline__ void subtile_mma(const __nv_bfloat16* bt, int n0, int lane,
                                            const unsigned a[4][4], float acc[8]) {
    const int m = lane >> 3;
    const int br = n0 + (lane & 7) + ((m >> 1) << 3);
    const int bk8 = m & 1;
#pragma unroll
    for (int ks = 0; ks < 4; ks++) {
        unsigned b[4];
        ldsm4(b, sptr(bt + br * 64 + (((2 * ks + bk8) ^ (br & 7)) << 3)));
        mma16816(acc, a[ks], b[0], b[1]);
        mma16816(acc + 4, a[ks], b[2], b[3]);
    }
}

// ---------------------------------------------------------------------------
// Prep: bf16 conversion of x and mask in one kernel
// ---------------------------------------------------------------------------
#define NX4 (BB * CX * NN * DD / 4)
#define NM4 (BB * C1 * NN * DD / 4)
__global__ void k_conv(const float* __restrict__ x, const float* __restrict__ mask) {
    int idx = blockIdx.x * blockDim.x + threadIdx.x;
    const float4* src;
    uint2* dst;
    int i;
    if (idx < NX4) { src = (const float4*)x; dst = (uint2*)g_xbf; i = idx; }
    else if (idx < NX4 + NM4) { src = (const float4*)mask; dst = (uint2*)g_mbf; i = idx - NX4; }
    else return;
    float4 v = src[i];
    uint2 u;
    u.x = packbf2(v.x, v.y);
    u.y = packbf2(v.z, v.w);
    dst[i] = u;
}

// ---------------------------------------------------------------------------
// k_S4: SINGLE-PASS. For 2 channels, 64-row tiles: compute logits once,
// write unnormalized exp(logit - P) as bf16 per channel, accumulate row sums
// Z in the same pass, write zi = 1/(16 Z) to g_Zi at the end.
// grid (itile=16, cg=8, b=4) = 512 blocks, 256 thr.
// ---------------------------------------------------------------------------
#define KS4_SMEM (2*64*64*2 + 2*2*64*64*2 + 2*64*4 + 2*64*2*4)

__global__ void __launch_bounds__(256, 3) k_S4() {
    extern __shared__ char sm[];
    __nv_bfloat16* xi  = (__nv_bfloat16*)sm;            // [2ch][64*64]
    __nv_bfloat16* xjb = xi + 2 * 64 * 64;              // [2buf][2ch][64*64]
    float* P  = (float*)(xjb + 2 * 2 * 64 * 64);        // [2][64]
    float* Zw = P + 2 * 64;                             // [2][64][2]

    const int tid = threadIdx.x, lane = tid & 31, w = tid >> 5;
    const int wr = w & 3, wc = w >> 2;
    const int itile = blockIdx.x, cg = blockIdx.y, b = blockIdx.z;

    const __nv_bfloat16* xc0 = g_xbf + (size_t)(b * CX + cg * 2) * NN * DD;
    const __nv_bfloat16* xc1 = xc0 + NN * DD;

    pf_tile64(xc0 + itile * 64 * 64, xi, tid);
    pf_tile64(xc1 + itile * 64 * 64, xi + 64 * 64, tid);
    CP_COMMIT();
    pf_tile64(xc0, xjb, tid);
    pf_tile64(xc1, xjb + 64 * 64, tid);
    CP_COMMIT();
    CP_WAIT1();
    __syncthreads();

    // P = ||row||^2 from bf16 values
    if (tid < 128) {
        int c = tid >> 6, r = tid & 63;
        const __nv_bfloat16* row = xi + c * 4096 + r * 64;
        float s = 0.f;
#pragma unroll
        for (int cc = 0; cc < 8; cc++) {
            const __nv_bfloat16* ch = row + ((cc ^ (r & 7)) << 3);
#pragma unroll
            for (int e = 0; e < 8; e++) {
                float v = __bfloat162float(ch[e]);
                s += v * v;
            }
        }
        P[c * 64 + r] = s;
    }
    __syncthreads();

    unsigned a0[4][4], a1[4][4];
    load_afrag(xi + wr * 16 * 64, lane, a0);
    load_afrag(xi + 4096 + wr * 16 * 64, lane, a1);

    const int lr0 = wr * 16 + (lane >> 2), lr1 = lr0 + 8;
    const float p00 = P[lr0], p01 = P[lr1], p10 = P[64 + lr0], p11 = P[64 + lr1];

    __nv_bfloat16* sp0 = g_Sp + (size_t)((cg * 2 + 0) * BB + b) * NN * NN
                              + (size_t)(itile * 64) * NN;
    __nv_bfloat16* sp1 = g_Sp + (size_t)((cg * 2 + 1) * BB + b) * NN * NN
                              + (size_t)(itile * 64) * NN;

    float z00 = 0.f, z01 = 0.f, z10 = 0.f, z11 = 0.f;

    for (int jt = 0; jt < 16; jt++) {
        if (jt < 15) {
            __nv_bfloat16* nb = xjb + ((jt + 1) & 1) * 8192;
            pf_tile64(xc0 + (jt + 1) * 64 * 64, nb, tid);
            pf_tile64(xc1 + (jt + 1) * 64 * 64, nb + 4096, tid);
            CP_COMMIT(); CP_WAIT1();
        } else CP_WAIT0();
        __syncthreads();
        const __nv_bfloat16* bt = xjb + (jt & 1) * 8192;

#pragma unroll
        for (int nn = 0; nn < 2; nn++) {
            const int n = wc * 2 + nn;
            const int cb = jt * 64 + n * 16 + 2 * (lane & 3);
            // channel 0
            {
                float acc[8] = {0.f, 0.f, 0.f, 0.f, 0.f, 0.f, 0.f, 0.f};
                subtile_mma(bt, n * 16, lane, a0, acc);
                float e0 = __expf(acc[0] - p00), e1 = __expf(acc[1] - p00);
                float e4 = __expf(acc[4] - p00), e5 = __expf(acc[5] - p00);
                float e2 = __expf(acc[2] - p01), e3 = __expf(acc[3] - p01);
                float e6 = __expf(acc[6] - p01), e7 = __expf(acc[7] - p01);
                z00 += (e0 + e1) + (e4 + e5);
                z01 += (e2 + e3) + (e6 + e7);
                *(unsigned*)(sp0 + (size_t)lr0 * NN + cb)     = packbf2(e0, e1);
                *(unsigned*)(sp0 + (size_t)lr0 * NN + cb + 8) = packbf2(e4, e5);
                *(unsigned*)(sp0 + (size_t)lr1 * NN + cb)     = packbf2(e2, e3);
                *(unsigned*)(sp0 + (size_t)lr1 * NN + cb + 8) = packbf2(e6, e7);
            }
            // channel 1
            {
                float acc[8] = {0.f, 0.f, 0.f, 0.f, 0.f, 0.f, 0.f, 0.f};
                subtile_mma(bt + 4096, n * 16, lane, a1, acc);
                float e0 = __expf(acc[0] - p10), e1 = __expf(acc[1] - p10);
                float e4 = __expf(acc[4] - p10), e5 = __expf(acc[5] - p10);
                float e2 = __expf(acc[2] - p11), e3 = __expf(acc[3] - p11);
                float e6 = __expf(acc[6] - p11), e7 = __expf(acc[7] - p11);
                z10 += (e0 + e1) + (e4 + e5);
                z11 += (e2 + e3) + (e6 + e7);
                *(unsigned*)(sp1 + (size_t)lr0 * NN + cb)     = packbf2(e0, e1);
                *(unsigned*)(sp1 + (size_t)lr0 * NN + cb + 8) = packbf2(e4, e5);
                *(unsigned*)(sp1 + (size_t)lr1 * NN + cb)     = packbf2(e2, e3);
                *(unsigned*)(sp1 + (size_t)lr1 * NN + cb + 8) = packbf2(e6, e7);
            }
        }
        __syncthreads();
    }

    // combine Z across quads + the 2 col-half warps, write zi
    z00 += __shfl_xor_sync(0xffffffffu, z00, 1); z00 += __shfl_xor_sync(0xffffffffu, z00, 2);
    z01 += __shfl_xor_sync(0xffffffffu, z01, 1); z01 += __shfl_xor_sync(0xffffffffu, z01, 2);
    z10 += __shfl_xor_sync(0xffffffffu, z10, 1); z10 += __shfl_xor_sync(0xffffffffu, z10, 2);
    z11 += __shfl_xor_sync(0xffffffffu, z11, 1); z11 += __shfl_xor_sync(0xffffffffu, z11, 2);
    if ((lane & 3) == 0) {
        Zw[lr0 * 2 + wc]       = z00;
        Zw[lr1 * 2 + wc]       = z01;
        Zw[128 + lr0 * 2 + wc] = z10;
        Zw[128 + lr1 * 2 + wc] = z11;
    }
    __syncthreads();
    if (tid < 128) {
        int c = tid >> 6, r = tid & 63;
        float zi = 1.f / (16.f * (Zw[c * 128 + r * 2] + Zw[c * 128 + r * 2 + 1]));
        g_Zi[(size_t)(b * CX + cg * 2 + c) * NN + itile * 64 + r] = zi;
    }
}

// ---------------------------------------------------------------------------
// k_sreduce3: one block per (b,row). S = sum_ch e_ch * zi_ch over 16 channels
// + mean of A over CA; write interleaved (S*SSCALE, Amean+0.01) pairs.
// ---------------------------------------------------------------------------
__global__ void __launch_bounds__(256) k_sreduce3(const float* __restrict__ A) {
    __shared__ float zi_s[CX];
    const int tid = threadIdx.x;
    const int b = blockIdx.x >> 10;
    const int row = blockIdx.x & 1023;

    if (tid < CX) zi_s[tid] = g_Zi[(size_t)(b * CX + tid) * NN + row];
    __syncthreads();

    // thread handles elements [4*tid, 4*tid+4) of this row
    float4 s = make_float4(0.f, 0.f, 0.f, 0.f);
#pragma unroll
    for (int ch = 0; ch < CX; ch++) {
        const __nv_bfloat16* sp = g_Sp + (size_t)(ch * BB + b) * NN * NN
                                       + (size_t)row * NN + 4 * tid;
        uint2 u = *(const uint2*)sp;
        __nv_bfloat162 h0 = *reinterpret_cast<__nv_bfloat162*>(&u.x);
        __nv_bfloat162 h1 = *reinterpret_cast<__nv_bfloat162*>(&u.y);
        float2 f0 = __bfloat1622float2(h0);
        float2 f1 = __bfloat1622float2(h1);
        const float z = zi_s[ch];
        s.x = fmaf(f0.x, z, s.x); s.y = fmaf(f0.y, z, s.y);
        s.z = fmaf(f1.x, z, s.z); s.w = fmaf(f1.y, z, s.w);
    }

    float4 a = make_float4(0.f, 0.f, 0.f, 0.f);
#pragma unroll
    for (int ch = 0; ch < CA; ch++) {
        const float4* ap = (const float4*)(A + (size_t)(b * CA + ch) * NN * NN
                                             + (size_t)row * NN) + tid;
        float4 v = *ap;
        a.x += v.x; a.y += v.y; a.z += v.z; a.w += v.w;
    }

    float4 o1, o2;
    o1.x = s.x * SSCALE; o1.y = a.x * 0.125f + 0.01f;
    o1.z = s.y * SSCALE; o1.w = a.y * 0.125f + 0.01f;
    o2.x = s.z * SSCALE; o2.y = a.z * 0.125f + 0.01f;
    o2.z = s.w * SSCALE; o2.w = a.w * 0.125f + 0.01f;
    float4* out = (float4*)(g_SA + ((size_t)b * NN + row) * NN * 2) + tid * 2;
    out[0] = o1;
    out[1] = o2;
}

// ---------------------------------------------------------------------------
// k_mm2: per (itile, cpair, b): 2 channels share a cp.async-pipelined SA
// stream through smem. grid (8, 8, 4) = 256 blocks, 2 blocks/SM. (UNCHANGED)
// ---------------------------------------------------------------------------
#define KMM2_SMEM (2*128*64*2 + 2*2*64*64*2 + 3*128*128)

__global__ void __launch_bounds__(256, 2) k_mm2(float* __restrict__ outA) {
    extern __shared__ char sm[];
    __nv_bfloat16* mi0 = (__nv_bfloat16*)sm;               // [128*64]
    __nv_bfloat16* mi1 = mi0 + 128 * 64;                   // [128*64]
    char* mjb = sm + 32768;                                // [2buf][2ch][8192B]
    char* sab = sm + 65536;                                // [3][128*128B]

    const int tid = threadIdx.x, lane = tid & 31, w = tid >> 5;
    const int itile = blockIdx.x, cpair = blockIdx.y, b = blockIdx.z;
    const int c0 = cpair * 2;

    const __nv_bfloat16* mc0 = g_mbf + (size_t)(b * C1 + c0) * NN * DD;
    const __nv_bfloat16* mc1 = mc0 + NN * DD;
    const float* saBase = g_SA + (size_t)(b * NN + itile * 128) * (NN * 2);

    pf_tile128(mc0 + itile * 128 * 64, mi0, tid);
    pf_tile128(mc1 + itile * 128 * 64, mi1, tid);
    pf_tile64(mc0, (__nv_bfloat16*)(mjb), tid);
    pf_tile64(mc1, (__nv_bfloat16*)(mjb + 8192), tid);
    pf_sa(saBase, sab, tid);
    CP_COMMIT();
    pf_sa(saBase + 32, sab + 16384, tid);
    CP_COMMIT();

    CP_WAIT1();
    __syncthreads();

    unsigned a0[4][4], a1[4][4];
    load_afrag(mi0 + w * 16 * 64, lane, a0);
    load_afrag(mi1 + w * 16 * 64, lane, a1);

    const int lr0 = w * 16 + (lane >> 2), lr1 = lr0 + 8;
    const int gr0 = itile * 128 + lr0, gr1 = itile * 128 + lr1;
    float* O00 = outA + ((size_t)(b * C1 + c0) * NN + gr0) * NN;
    float* O01 = outA + ((size_t)(b * C1 + c0) * NN + gr1) * NN;
    float* O10 = O00 + (size_t)NN * NN;
    float* O11 = O01 + (size_t)NN * NN;

    const int lq = 2 * (lane & 3);
    const int saoff0 = lr0 * 128 + (lane & 3) * 16;
    const int saoff1 = lr1 * 128 + (lane & 3) * 16;

    int sidx = 0;
    int pidx = 2;

    for (int k = 0; k < 64; k++) {
        const int jt = k >> 2, n = k & 3;

        CP_WAIT1();
        __syncthreads();

        if (k < 62) {
            pf_sa(saBase + (k + 2) * 32, sab + pidx * 16384, tid);
            if (n == 0 && jt < 15) {
                char* nb = mjb + ((jt + 1) & 1) * 16384;
                pf_tile64(mc0 + (jt + 1) * 4096, (__nv_bfloat16*)nb, tid);
                pf_tile64(mc1 + (jt + 1) * 4096, (__nv_bfloat16*)(nb + 8192), tid);
            }
        }
        CP_COMMIT();

        const char* sap = sab + sidx * 16384;
        const float4 q0 = *(const float4*)(sap + saoff0);
        const float4 q1 = *(const float4*)(sap + saoff0 + 64);
        const float4 q2 = *(const float4*)(sap + saoff1);
        const float4 q3 = *(const float4*)(sap + saoff1 + 64);

        const __nv_bfloat16* bt0 = (const __nv_bfloat16*)(mjb + (jt & 1) * 16384);
        const __nv_bfloat16* bt1 = (const __nv_bfloat16*)(mjb + (jt & 1) * 16384 + 8192);
        const int cb = jt * 64 + n * 16 + lq;

        {
            float acc[8] = {0.f, 0.f, 0.f, 0.f, 0.f, 0.f, 0.f, 0.f};
            subtile_mma(bt0, n * 16, lane, a0, acc);
            float o0 = fmaf(0.01f, tanhap(q0.x * acc[0]), q0.y);
            float o1 = fmaf(0.01f, tanhap(q0.z * acc[1]), q0.w);
            float o4 = fmaf(0.01f, tanhap(q1.x * acc[4]), q1.y);
            float o5 = fmaf(0.01f, tanhap(q1.z * acc[5]), q1.w);
            float o2 = fmaf(0.01f, tanhap(q2.x * acc[2]), q2.y);
            float o3 = fmaf(0.01f, tanhap(q2.z * acc[3]), q2.w);
            float o6 = fmaf(0.01f, tanhap(q3.x * acc[6]), q3.y);
            float o7 = fmaf(0.01f, tanhap(q3.z * acc[7]), q3.w);
            *(float2*)(O00 + cb)     = make_float2(o0, o1);
            *(float2*)(O00 + cb + 8) = make_float2(o4, o5);
            *(float2*)(O01 + cb)     = make_float2(o2, o3);
            *(float2*)(O01 + cb + 8) = make_float2(o6, o7);
        }
        {
            float acc[8] = {0.f, 0.f, 0.f, 0.f, 0.f, 0.f, 0.f, 0.f};
            subtile_mma(bt1, n * 16, lane, a1, acc);
            float o0 = fmaf(0.01f, tanhap(q0.x * acc[0]), q0.y);
            float o1 = fmaf(0.01f, tanhap(q0.z * acc[1]), q0.w);
            float o4 = fmaf(0.01f, tanhap(q1.x * acc[4]), q1.y);
            float o5 = fmaf(0.01f, tanhap(q1.z * acc[5]), q1.w);
            float o2 = fmaf(0.01f, tanhap(q2.x * acc[2]), q2.y);
            float o3 = fmaf(0.01f, tanhap(q2.z * acc[3]), q2.w);
            float o6 = fmaf(0.01f, tanhap(q3.x * acc[6]), q3.y);
            float o7 = fmaf(0.01f, tanhap(q3.z * acc[7]), q3.w);
            *(float2*)(O10 + cb)     = make_float2(o0, o1);
            *(float2*)(O10 + cb + 8) = make_float2(o4, o5);
            *(float2*)(O11 + cb)     = make_float2(o2, o3);
            *(float2*)(O11 + cb + 8) = make_float2(o6, o7);
        }

        sidx = (sidx == 2) ? 0 : sidx + 1;
        pidx = (pidx == 2) ? 0 : pidx + 1;
    }
}

// ---------------------------------------------------------------------------
// k_topk: warp per row. Batch-load row (MLP=8), rare-branch top-5, REDUX
// merge, gather mask rows + max. (UNCHANGED)
// ---------------------------------------------------------------------------
__device__ __forceinline__ void ins5(float x, int i, float v[5], int ix[5]) {
#pragma unroll
    for (int p = 0; p < 5; p++) {
        if (x > v[p]) {
            float tv = v[p]; v[p] = x; x = tv;
            int ti = ix[p]; ix[p] = i; i = ti;
        }
    }
}

__device__ __forceinline__ void head5(const float v[5], const int ix[5], int ptr,
                                      float& hv, int& hi) {
    hv = NEGINF; hi = 0x7fffffff;
    if (ptr == 0)      { hv = v[0]; hi = ix[0]; }
    else if (ptr == 1) { hv = v[1]; hi = ix[1]; }
    else if (ptr == 2) { hv = v[2]; hi = ix[2]; }
    else if (ptr == 3) { hv = v[3]; hi = ix[3]; }
    else if (ptr == 4) { hv = v[4]; hi = ix[4]; }
}

__global__ void __launch_bounds__(256) k_topk(const float* __restrict__ outA,
                                              const float* __restrict__ mask,
                                              float* __restrict__ outM) {
    const int lane = threadIdx.x & 31;
    const int g = blockIdx.x * 8 + (threadIdx.x >> 5);
    const float4* Ar = (const float4*)(outA + (size_t)g * NN);

    float4 t[8];
#pragma unroll
    for (int k = 0; k < 8; k++) t[k] = Ar[k * 32 + lane];

    float v[5]; int ix[5];
#pragma unroll
    for (int p = 0; p < 5; p++) { v[p] = NEGINF; ix[p] = 0x7fffffff; }
    float vmin = NEGINF;
#pragma unroll
    for (int k = 0; k < 8; k++) {
        float m = fmaxf(fmaxf(t[k].x, t[k].y), fmaxf(t[k].z, t[k].w));
        if (m > vmin) {
            const int cb = (k * 32 + lane) * 4;
            ins5(t[k].x, cb, v, ix);
            ins5(t[k].y, cb + 1, v, ix);
            ins5(t[k].z, cb + 2, v, ix);
            ins5(t[k].w, cb + 3, v, ix);
            vmin = v[4];
        }
    }

    int wout[5];
    int ptr = 0;
#pragma unroll
    for (int t5 = 0; t5 < 5; t5++) {
        float hv; int hi;
        head5(v, ix, ptr, hv, hi);
        unsigned key = ordf(hv);
        unsigned mx = __reduce_max_sync(0xffffffffu, key);
        unsigned ball = __ballot_sync(0xffffffffu, key == mx);
        int src = __ffs((int)ball) - 1;
        wout[t5] = __shfl_sync(0xffffffffu, hi, src);
        if (lane == src) ptr++;
    }

    const int bc = g >> 10;
    const float* mkb = mask + (size_t)bc * (NN * DD);
    float m0 = NEGINF, m1 = NEGINF;
#pragma unroll
    for (int p = 0; p < 5; p++) {
        const float* mr = mkb + (size_t)wout[p] * DD;
        m0 = fmaxf(m0, mr[lane]);
        m1 = fmaxf(m1, mr[lane + 32]);
    }
    outM[(size_t)g * DD + lane]      = m0;
    outM[(size_t)g * DD + lane + 32] = m1;
}

// ---------------------------------------------------------------------------
extern "C" void kernel_launch(void* const* d_in, const int* in_sizes, int n_in,
                              void* d_out, int out_size) {
    (void)in_sizes; (void)n_in; (void)out_size;
    const float* x    = (const float*)d_in[0];
    const float* A    = (const float*)d_in[1];
    const float* mask = (const float*)d_in[2];
    float* outA = (float*)d_out;
    float* outM = outA + (size_t)BB * C1 * NN * NN;

    cudaFuncSetAttribute(k_S4, cudaFuncAttributeMaxDynamicSharedMemorySize, KS4_SMEM);
    cudaFuncSetAttribute(k_mm2, cudaFuncAttributeMaxDynamicSharedMemorySize, KMM2_SMEM);

    k_conv<<<(NX4 + NM4 + 255) / 256, 256>>>(x, mask);
    k_S4<<<dim3(16, 8, BB), 256, KS4_SMEM>>>();
    k_sreduce3<<<BB * NN, 256>>>(A);
    k_mm2<<<dim3(8, 8, BB), 256, KMM2_SMEM>>>(outA);
    k_topk<<<BB * C1 * NN / 8, 256>>>(outA, mask, outM);
}

// round 14
// speedup vs baseline: 1.3411x; 1.0656x over previous
#include <cuda_runtime.h>
#include <cuda_bf16.h>

// Problem constants
#define BB  4
#define CX  16
#define CA  8
#define C1  16
#define NN  1024
#define DD  64
#define NEGINF (-3.402823466e38f)

// 0.02*sigmoid(z) = 0.01 + 0.01*tanh(z/2); z = S*mm/sqrt(10)
#define SSCALE 0.15811388300841898f

// Scratch (static __device__ arrays; no dynamic allocation)
__device__ __align__(16) __nv_bfloat16 g_Sp[16u * BB * NN * NN];   // 134 MB per-channel exp (bf16)
__device__ __align__(16) float g_Zi[BB * CX * NN];                 // per-(b,ch,row) 1/(16Z)
__device__ __align__(16) float g_SA[2u * BB * NN * NN];            // 33.6 MB (S',A') interleaved
__device__ __align__(16) float g_max[BB * C1 * NN * 16];           // 4 MB per-row per-64col chunk max
__device__ __align__(16) __nv_bfloat16 g_xbf[BB * CX * NN * DD];   // 8.4 MB
__device__ __align__(16) __nv_bfloat16 g_mbf[BB * C1 * NN * DD];   // 8.4 MB

// ---------------------------------------------------------------------------
// PTX helpers
// ---------------------------------------------------------------------------
__device__ __forceinline__ unsigned sptr(const void* p) {
    return (unsigned)__cvta_generic_to_shared(p);
}

__device__ __forceinline__ void ldsm4(unsigned a[4], unsigned addr) {
    asm volatile("ldmatrix.sync.aligned.m8n8.x4.shared.b16 {%0,%1,%2,%3}, [%4];"
                 : "=r"(a[0]), "=r"(a[1]), "=r"(a[2]), "=r"(a[3]) : "r"(addr));
}

__device__ __forceinline__ void mma16816(float c[4], const unsigned a[4],
                                         unsigned b0, unsigned b1) {
    asm volatile(
        "mma.sync.aligned.m16n8k16.row.col.f32.bf16.bf16.f32 "
        "{%0,%1,%2,%3}, {%4,%5,%6,%7}, {%8,%9}, {%0,%1,%2,%3};"
        : "+f"(c[0]), "+f"(c[1]), "+f"(c[2]), "+f"(c[3])
        : "r"(a[0]), "r"(a[1]), "r"(a[2]), "r"(a[3]), "r"(b0), "r"(b1));
}

__device__ __forceinline__ void cpasync16(unsigned dst, const void* src) {
    asm volatile("cp.async.cg.shared.global [%0], [%1], 16;" :: "r"(dst), "l"(src));
}
#define CP_COMMIT() asm volatile("cp.async.commit_group;")
#define CP_WAIT1()  asm volatile("cp.async.wait_group 1;")
#define CP_WAIT0()  asm volatile("cp.async.wait_group 0;")

__device__ __forceinline__ float tanhap(float x) {
    float r;
    asm("tanh.approx.f32 %0, %1;" : "=f"(r) : "f"(x));
    return r;
}

__device__ __forceinline__ unsigned packbf2(float a, float b) {
    __nv_bfloat162 h = __floats2bfloat162_rn(a, b);
    return *reinterpret_cast<unsigned*>(&h);
}

// float -> order-preserving uint
__device__ __forceinline__ unsigned ordf(float f) {
    unsigned u = __float_as_uint(f);
    return (u & 0x80000000u) ? ~u : (u | 0x80000000u);
}

// ---------------------------------------------------------------------------
// Swizzled bf16 tiles: [rows][64] bf16, 128B/row; 16B chunk' = chunk ^ (row&7)
// ---------------------------------------------------------------------------
__device__ __forceinline__ void pf_tile128(const __nv_bfloat16* src,
                                           __nv_bfloat16* dst, int tid) {
#pragma unroll
    for (int q = 0; q < 4; q++) {
        int id = tid + q * 256;
        int r = id >> 3, cc = id & 7;
        cpasync16(sptr(dst + r * 64 + ((cc ^ (r & 7)) << 3)), src + r * 64 + cc * 8);
    }
}

__device__ __forceinline__ void pf_tile64(const __nv_bfloat16* src,
                                          __nv_bfloat16* dst, int tid) {
#pragma unroll
    for (int q = 0; q < 2; q++) {
        int id = tid + q * 256;
        int r = id >> 3, cc = id & 7;
        cpasync16(sptr(dst + r * 64 + ((cc ^ (r & 7)) << 3)), src + r * 64 + cc * 8);
    }
}

// SA subtile prefetch: 128 rows x 128 bytes into smem stride 128
__device__ __forceinline__ void pf_sa(const float* src, char* dst, int tid) {
#pragma unroll
    for (int q = 0; q < 4; q++) {
        int id = tid + q * 256;
        int r = id >> 3, c = id & 7;
        cpasync16(sptr(dst + r * 128 + c * 16),
                  (const char*)src + (size_t)r * 8192 + c * 16);
    }
}

// A fragments for a 16-row slice, cached in regs
__device__ __forceinline__ void load_afrag(const __nv_bfloat16* xi16, int lane,
                                           unsigned a[4][4]) {
    const int ar = (lane & 7) + (((lane >> 3) & 1) << 3);
    const int ak8 = lane >> 4;
#pragma unroll
    for (int ks = 0; ks < 4; ks++)
        ldsm4(a[ks], sptr(xi16 + ar * 64 + (((2 * ks + ak8) ^ (ar & 7)) << 3)));
}

// acc[8] += A(16x64) * B(rows n0..n0+15 of 64x64 tile)^T
__device__ __forceinline__ void subtile_mma(const __nv_bfloat16* bt, int n0, int lane,
                                            const unsigned a[4][4], float acc[8]) {
    const int m = lane >> 3;
    const int br = n0 + (lane & 7) + ((m >> 1) << 3);
    const int bk8 = m & 1;
#pragma unroll
    for (int ks = 0; ks < 4; ks++) {
        unsigned b[4];
        ldsm4(b, sptr(bt + br * 64 + (((2 * ks + bk8) ^ (br & 7)) << 3)));
        mma16816(acc, a[ks], b[0], b[1]);
        mma16816(acc + 4, a[ks], b[2], b[3]);
    }
}

// ---------------------------------------------------------------------------
// Prep: bf16 conversion of x and mask in one kernel
// ---------------------------------------------------------------------------
#define NX4 (BB * CX * NN * DD / 4)
#define NM4 (BB * C1 * NN * DD / 4)
__global__ void k_conv(const float* __restrict__ x, const float* __restrict__ mask) {
    int idx = blockIdx.x * blockDim.x + threadIdx.x;
    const float4* src;
    uint2* dst;
    int i;
    if (idx < NX4) { src = (const float4*)x; dst = (uint2*)g_xbf; i = idx; }
    else if (idx < NX4 + NM4) { src = (const float4*)mask; dst = (uint2*)g_mbf; i = idx - NX4; }
    else return;
    float4 v = src[i];
    uint2 u;
    u.x = packbf2(v.x, v.y);
    u.y = packbf2(v.z, v.w);
    dst[i] = u;
}

// ---------------------------------------------------------------------------
// k_S4: SINGLE-PASS softmax exp + Z. grid (16, 8, 4), 256 thr. (UNCHANGED)
// ---------------------------------------------------------------------------
#define KS4_SMEM (2*64*64*2 + 2*2*64*64*2 + 2*64*4 + 2*64*2*4)

__global__ void __launch_bounds__(256, 3) k_S4() {
    extern __shared__ char sm[];
    __nv_bfloat16* xi  = (__nv_bfloat16*)sm;
    __nv_bfloat16* xjb = xi + 2 * 64 * 64;
    float* P  = (float*)(xjb + 2 * 2 * 64 * 64);
    float* Zw = P + 2 * 64;

    const int tid = threadIdx.x, lane = tid & 31, w = tid >> 5;
    const int wr = w & 3, wc = w >> 2;
    const int itile = blockIdx.x, cg = blockIdx.y, b = blockIdx.z;

    const __nv_bfloat16* xc0 = g_xbf + (size_t)(b * CX + cg * 2) * NN * DD;
    const __nv_bfloat16* xc1 = xc0 + NN * DD;

    pf_tile64(xc0 + itile * 64 * 64, xi, tid);
    pf_tile64(xc1 + itile * 64 * 64, xi + 64 * 64, tid);
    CP_COMMIT();
    pf_tile64(xc0, xjb, tid);
    pf_tile64(xc1, xjb + 64 * 64, tid);
    CP_COMMIT();
    CP_WAIT1();
    __syncthreads();

    if (tid < 128) {
        int c = tid >> 6, r = tid & 63;
        const __nv_bfloat16* row = xi + c * 4096 + r * 64;
        float s = 0.f;
#pragma unroll
        for (int cc = 0; cc < 8; cc++) {
            const __nv_bfloat16* ch = row + ((cc ^ (r & 7)) << 3);
#pragma unroll
            for (int e = 0; e < 8; e++) {
                float v = __bfloat162float(ch[e]);
                s += v * v;
            }
        }
        P[c * 64 + r] = s;
    }
    __syncthreads();

    unsigned a0[4][4], a1[4][4];
    load_afrag(xi + wr * 16 * 64, lane, a0);
    load_afrag(xi + 4096 + wr * 16 * 64, lane, a1);

    const int lr0 = wr * 16 + (lane >> 2), lr1 = lr0 + 8;
    const float p00 = P[lr0], p01 = P[lr1], p10 = P[64 + lr0], p11 = P[64 + lr1];

    __nv_bfloat16* sp0 = g_Sp + (size_t)((cg * 2 + 0) * BB + b) * NN * NN
                              + (size_t)(itile * 64) * NN;
    __nv_bfloat16* sp1 = g_Sp + (size_t)((cg * 2 + 1) * BB + b) * NN * NN
                              + (size_t)(itile * 64) * NN;

    float z00 = 0.f, z01 = 0.f, z10 = 0.f, z11 = 0.f;

    for (int jt = 0; jt < 16; jt++) {
        if (jt < 15) {
            __nv_bfloat16* nb = xjb + ((jt + 1) & 1) * 8192;
            pf_tile64(xc0 + (jt + 1) * 64 * 64, nb, tid);
            pf_tile64(xc1 + (jt + 1) * 64 * 64, nb + 4096, tid);
            CP_COMMIT(); CP_WAIT1();
        } else CP_WAIT0();
        __syncthreads();
        const __nv_bfloat16* bt = xjb + (jt & 1) * 8192;

#pragma unroll
        for (int nn = 0; nn < 2; nn++) {
            const int n = wc * 2 + nn;
            const int cb = jt * 64 + n * 16 + 2 * (lane & 3);
            {
                float acc[8] = {0.f, 0.f, 0.f, 0.f, 0.f, 0.f, 0.f, 0.f};
                subtile_mma(bt, n * 16, lane, a0, acc);
                float e0 = __expf(acc[0] - p00), e1 = __expf(acc[1] - p00);
                float e4 = __expf(acc[4] - p00), e5 = __expf(acc[5] - p00);
                float e2 = __expf(acc[2] - p01), e3 = __expf(acc[3] - p01);
                float e6 = __expf(acc[6] - p01), e7 = __expf(acc[7] - p01);
                z00 += (e0 + e1) + (e4 + e5);
                z01 += (e2 + e3) + (e6 + e7);
                *(unsigned*)(sp0 + (size_t)lr0 * NN + cb)     = packbf2(e0, e1);
                *(unsigned*)(sp0 + (size_t)lr0 * NN + cb + 8) = packbf2(e4, e5);
                *(unsigned*)(sp0 + (size_t)lr1 * NN + cb)     = packbf2(e2, e3);
                *(unsigned*)(sp0 + (size_t)lr1 * NN + cb + 8) = packbf2(e6, e7);
            }
            {
                float acc[8] = {0.f, 0.f, 0.f, 0.f, 0.f, 0.f, 0.f, 0.f};
                subtile_mma(bt + 4096, n * 16, lane, a1, acc);
                float e0 = __expf(acc[0] - p10), e1 = __expf(acc[1] - p10);
                float e4 = __expf(acc[4] - p10), e5 = __expf(acc[5] - p10);
                float e2 = __expf(acc[2] - p11), e3 = __expf(acc[3] - p11);
                float e6 = __expf(acc[6] - p11), e7 = __expf(acc[7] - p11);
                z10 += (e0 + e1) + (e4 + e5);
                z11 += (e2 + e3) + (e6 + e7);
                *(unsigned*)(sp1 + (size_t)lr0 * NN + cb)     = packbf2(e0, e1);
                *(unsigned*)(sp1 + (size_t)lr0 * NN + cb + 8) = packbf2(e4, e5);
                *(unsigned*)(sp1 + (size_t)lr1 * NN + cb)     = packbf2(e2, e3);
                *(unsigned*)(sp1 + (size_t)lr1 * NN + cb + 8) = packbf2(e6, e7);
            }
        }
        __syncthreads();
    }

    z00 += __shfl_xor_sync(0xffffffffu, z00, 1); z00 += __shfl_xor_sync(0xffffffffu, z00, 2);
    z01 += __shfl_xor_sync(0xffffffffu, z01, 1); z01 += __shfl_xor_sync(0xffffffffu, z01, 2);
    z10 += __shfl_xor_sync(0xffffffffu, z10, 1); z10 += __shfl_xor_sync(0xffffffffu, z10, 2);
    z11 += __shfl_xor_sync(0xffffffffu, z11, 1); z11 += __shfl_xor_sync(0xffffffffu, z11, 2);
    if ((lane & 3) == 0) {
        Zw[lr0 * 2 + wc]       = z00;
        Zw[lr1 * 2 + wc]       = z01;
        Zw[128 + lr0 * 2 + wc] = z10;
        Zw[128 + lr1 * 2 + wc] = z11;
    }
    __syncthreads();
    if (tid < 128) {
        int c = tid >> 6, r = tid & 63;
        float zi = 1.f / (16.f * (Zw[c * 128 + r * 2] + Zw[c * 128 + r * 2 + 1]));
        g_Zi[(size_t)(b * CX + cg * 2 + c) * NN + itile * 64 + r] = zi;
    }
}

// ---------------------------------------------------------------------------
// k_sreduce3: one block per (b,row). (UNCHANGED)
// ---------------------------------------------------------------------------
__global__ void __launch_bounds__(256) k_sreduce3(const float* __restrict__ A) {
    __shared__ float zi_s[CX];
    const int tid = threadIdx.x;
    const int b = blockIdx.x >> 10;
    const int row = blockIdx.x & 1023;

    if (tid < CX) zi_s[tid] = g_Zi[(size_t)(b * CX + tid) * NN + row];
    __syncthreads();

    float4 s = make_float4(0.f, 0.f, 0.f, 0.f);
#pragma unroll
    for (int ch = 0; ch < CX; ch++) {
        const __nv_bfloat16* sp = g_Sp + (size_t)(ch * BB + b) * NN * NN
                                       + (size_t)row * NN + 4 * tid;
        uint2 u = *(const uint2*)sp;
        __nv_bfloat162 h0 = *reinterpret_cast<__nv_bfloat162*>(&u.x);
        __nv_bfloat162 h1 = *reinterpret_cast<__nv_bfloat162*>(&u.y);
        float2 f0 = __bfloat1622float2(h0);
        float2 f1 = __bfloat1622float2(h1);
        const float z = zi_s[ch];
        s.x = fmaf(f0.x, z, s.x); s.y = fmaf(f0.y, z, s.y);
        s.z = fmaf(f1.x, z, s.z); s.w = fmaf(f1.y, z, s.w);
    }

    float4 a = make_float4(0.f, 0.f, 0.f, 0.f);
#pragma unroll
    for (int ch = 0; ch < CA; ch++) {
        const float4* ap = (const float4*)(A + (size_t)(b * CA + ch) * NN * NN
                                             + (size_t)row * NN) + tid;
        float4 v = *ap;
        a.x += v.x; a.y += v.y; a.z += v.z; a.w += v.w;
    }

    float4 o1, o2;
    o1.x = s.x * SSCALE; o1.y = a.x * 0.125f + 0.01f;
    o1.z = s.y * SSCALE; o1.w = a.y * 0.125f + 0.01f;
    o2.x = s.z * SSCALE; o2.y = a.z * 0.125f + 0.01f;
    o2.z = s.w * SSCALE; o2.w = a.w * 0.125f + 0.01f;
    float4* out = (float4*)(g_SA + ((size_t)b * NN + row) * NN * 2) + tid * 2;
    out[0] = o1;
    out[1] = o2;
}

// ---------------------------------------------------------------------------
// k_mm2: 2 channels share cp.async-pipelined SA via smem; ALSO tracks exact
// per-(row,ch,jt-chunk) max of outputs -> g_max (for pruned topk).
// grid (8, 8, 4) = 256 blocks, 2 blocks/SM.
// ---------------------------------------------------------------------------
#define KMM2_SMEM (2*128*64*2 + 2*2*64*64*2 + 3*128*128)

__global__ void __launch_bounds__(256, 2) k_mm2(float* __restrict__ outA) {
    extern __shared__ char sm[];
    __nv_bfloat16* mi0 = (__nv_bfloat16*)sm;
    __nv_bfloat16* mi1 = mi0 + 128 * 64;
    char* mjb = sm + 32768;
    char* sab = sm + 65536;

    const int tid = threadIdx.x, lane = tid & 31, w = tid >> 5;
    const int itile = blockIdx.x, cpair = blockIdx.y, b = blockIdx.z;
    const int c0 = cpair * 2;

    const __nv_bfloat16* mc0 = g_mbf + (size_t)(b * C1 + c0) * NN * DD;
    const __nv_bfloat16* mc1 = mc0 + NN * DD;
    const float* saBase = g_SA + (size_t)(b * NN + itile * 128) * (NN * 2);

    pf_tile128(mc0 + itile * 128 * 64, mi0, tid);
    pf_tile128(mc1 + itile * 128 * 64, mi1, tid);
    pf_tile64(mc0, (__nv_bfloat16*)(mjb), tid);
    pf_tile64(mc1, (__nv_bfloat16*)(mjb + 8192), tid);
    pf_sa(saBase, sab, tid);
    CP_COMMIT();
    pf_sa(saBase + 32, sab + 16384, tid);
    CP_COMMIT();

    CP_WAIT1();
    __syncthreads();

    unsigned a0[4][4], a1[4][4];
    load_afrag(mi0 + w * 16 * 64, lane, a0);
    load_afrag(mi1 + w * 16 * 64, lane, a1);

    const int lr0 = w * 16 + (lane >> 2), lr1 = lr0 + 8;
    const int gr0 = itile * 128 + lr0, gr1 = itile * 128 + lr1;
    float* O00 = outA + ((size_t)(b * C1 + c0) * NN + gr0) * NN;
    float* O01 = outA + ((size_t)(b * C1 + c0) * NN + gr1) * NN;
    float* O10 = O00 + (size_t)NN * NN;
    float* O11 = O01 + (size_t)NN * NN;

    // g_max row bases
    float* MX00 = g_max + ((size_t)(b * C1 + c0) * NN + gr0) * 16;
    float* MX01 = g_max + ((size_t)(b * C1 + c0) * NN + gr1) * 16;
    float* MX10 = MX00 + (size_t)NN * 16;
    float* MX11 = MX01 + (size_t)NN * 16;

    const int lq = 2 * (lane & 3);
    const int saoff0 = lr0 * 128 + (lane & 3) * 16;
    const int saoff1 = lr1 * 128 + (lane & 3) * 16;

    int sidx = 0;
    int pidx = 2;

    // per-jt running maxima: [ch][rowhalf]
    float jm00 = NEGINF, jm01 = NEGINF, jm10 = NEGINF, jm11 = NEGINF;

    for (int k = 0; k < 64; k++) {
        const int jt = k >> 2, n = k & 3;

        CP_WAIT1();
        __syncthreads();

        if (k < 62) {
            pf_sa(saBase + (k + 2) * 32, sab + pidx * 16384, tid);
            if (n == 0 && jt < 15) {
                char* nb = mjb + ((jt + 1) & 1) * 16384;
                pf_tile64(mc0 + (jt + 1) * 4096, (__nv_bfloat16*)nb, tid);
                pf_tile64(mc1 + (jt + 1) * 4096, (__nv_bfloat16*)(nb + 8192), tid);
            }
        }
        CP_COMMIT();

        const char* sap = sab + sidx * 16384;
        const float4 q0 = *(const float4*)(sap + saoff0);
        const float4 q1 = *(const float4*)(sap + saoff0 + 64);
        const float4 q2 = *(const float4*)(sap + saoff1);
        const float4 q3 = *(const float4*)(sap + saoff1 + 64);

        const __nv_bfloat16* bt0 = (const __nv_bfloat16*)(mjb + (jt & 1) * 16384);
        const __nv_bfloat16* bt1 = (const __nv_bfloat16*)(mjb + (jt & 1) * 16384 + 8192);
        const int cb = jt * 64 + n * 16 + lq;

        {
            float acc[8] = {0.f, 0.f, 0.f, 0.f, 0.f, 0.f, 0.f, 0.f};
            subtile_mma(bt0, n * 16, lane, a0, acc);
            float o0 = fmaf(0.01f, tanhap(q0.x * acc[0]), q0.y);
            float o1 = fmaf(0.01f, tanhap(q0.z * acc[1]), q0.w);
            float o4 = fmaf(0.01f, tanhap(q1.x * acc[4]), q1.y);
            float o5 = fmaf(0.01f, tanhap(q1.z * acc[5]), q1.w);
            float o2 = fmaf(0.01f, tanhap(q2.x * acc[2]), q2.y);
            float o3 = fmaf(0.01f, tanhap(q2.z * acc[3]), q2.w);
            float o6 = fmaf(0.01f, tanhap(q3.x * acc[6]), q3.y);
            float o7 = fmaf(0.01f, tanhap(q3.z * acc[7]), q3.w);
            *(float2*)(O00 + cb)     = make_float2(o0, o1);
            *(float2*)(O00 + cb + 8) = make_float2(o4, o5);
            *(float2*)(O01 + cb)     = make_float2(o2, o3);
            *(float2*)(O01 + cb + 8) = make_float2(o6, o7);
            jm00 = fmaxf(jm00, fmaxf(fmaxf(o0, o1), fmaxf(o4, o5)));
            jm01 = fmaxf(jm01, fmaxf(fmaxf(o2, o3), fmaxf(o6, o7)));
        }
        {
            float acc[8] = {0.f, 0.f, 0.f, 0.f, 0.f, 0.f, 0.f, 0.f};
            subtile_mma(bt1, n * 16, lane, a1, acc);
            float o0 = fmaf(0.01f, tanhap(q0.x * acc[0]), q0.y);
            float o1 = fmaf(0.01f, tanhap(q0.z * acc[1]), q0.w);
            float o4 = fmaf(0.01f, tanhap(q1.x * acc[4]), q1.y);
            float o5 = fmaf(0.01f, tanhap(q1.z * acc[5]), q1.w);
            float o2 = fmaf(0.01f, tanhap(q2.x * acc[2]), q2.y);
            float o3 = fmaf(0.01f, tanhap(q2.z * acc[3]), q2.w);
            float o6 = fmaf(0.01f, tanhap(q3.x * acc[6]), q3.y);
            float o7 = fmaf(0.01f, tanhap(q3.z * acc[7]), q3.w);
            *(float2*)(O10 + cb)     = make_float2(o0, o1);
            *(float2*)(O10 + cb + 8) = make_float2(o4, o5);
            *(float2*)(O11 + cb)     = make_float2(o2, o3);
            *(float2*)(O11 + cb + 8) = make_float2(o6, o7);
            jm10 = fmaxf(jm10, fmaxf(fmaxf(o0, o1), fmaxf(o4, o5)));
            jm11 = fmaxf(jm11, fmaxf(fmaxf(o2, o3), fmaxf(o6, o7)));
        }

        if (n == 3) {
            // quad-reduce the 4 jt maxima, lane q==0 of each quad stores
            jm00 = fmaxf(jm00, __shfl_xor_sync(0xffffffffu, jm00, 1));
            jm00 = fmaxf(jm00, __shfl_xor_sync(0xffffffffu, jm00, 2));
            jm01 = fmaxf(jm01, __shfl_xor_sync(0xffffffffu, jm01, 1));
            jm01 = fmaxf(jm01, __shfl_xor_sync(0xffffffffu, jm01, 2));
            jm10 = fmaxf(jm10, __shfl_xor_sync(0xffffffffu, jm10, 1));
            jm10 = fmaxf(jm10, __shfl_xor_sync(0xffffffffu, jm10, 2));
            jm11 = fmaxf(jm11, __shfl_xor_sync(0xffffffffu, jm11, 1));
            jm11 = fmaxf(jm11, __shfl_xor_sync(0xffffffffu, jm11, 2));
            if ((lane & 3) == 0) {
                MX00[jt] = jm00;
                MX01[jt] = jm01;
                MX10[jt] = jm10;
                MX11[jt] = jm11;
            }
            jm00 = NEGINF; jm01 = NEGINF; jm10 = NEGINF; jm11 = NEGINF;
        }

        sidx = (sidx == 2) ? 0 : sidx + 1;
        pidx = (pidx == 2) ? 0 : pidx + 1;
    }
}

// ---------------------------------------------------------------------------
// k_topk2: warp per row. Read 16 exact chunk maxima, T = 5th largest; read
// only chunks with max >= T (provably contains all top-5 incl. ties);
// rare-branch top-5 + REDUX merge (min index on ties); gather + max.
// ---------------------------------------------------------------------------
__device__ __forceinline__ void ins5(float x, int i, float v[5], int ix[5]) {
#pragma unroll
    for (int p = 0; p < 5; p++) {
        if (x > v[p]) {
            float tv = v[p]; v[p] = x; x = tv;
            int ti = ix[p]; ix[p] = i; i = ti;
        }
    }
}

__device__ __forceinline__ void head5(const float v[5], const int ix[5], int ptr,
                                      float& hv, int& hi) {
    hv = NEGINF; hi = 0x7fffffff;
    if (ptr == 0)      { hv = v[0]; hi = ix[0]; }
    else if (ptr == 1) { hv = v[1]; hi = ix[1]; }
    else if (ptr == 2) { hv = v[2]; hi = ix[2]; }
    else if (ptr == 3) { hv = v[3]; hi = ix[3]; }
    else if (ptr == 4) { hv = v[4]; hi = ix[4]; }
}

__global__ void __launch_bounds__(256) k_topk2(const float* __restrict__ outA,
                                               const float* __restrict__ mask,
                                               float* __restrict__ outM) {
    const int lane = threadIdx.x & 31;
    const int g = blockIdx.x * 8 + (threadIdx.x >> 5);   // global row id

    // chunk maxima (lanes 0..15 real)
    const float* tab = g_max + (size_t)g * 16;
    float tv = (lane < 16) ? tab[lane] : NEGINF;
    const unsigned myord = ordf(tv);

    // T = 5th largest chunk max (with multiplicity)
    unsigned work = myord;
    unsigned Tord = 0;
#pragma unroll
    for (int t = 0; t < 5; t++) {
        Tord = __reduce_max_sync(0xffffffffu, work);
        unsigned ball = __ballot_sync(0xffffffffu, work == Tord);
        int src = __ffs((int)ball) - 1;
        if (lane == src) work = 0;   // remove one instance
    }
    unsigned sel = __ballot_sync(0xffffffffu, myord >= Tord);

    const float* Ar = outA + (size_t)g * NN;
    float v[5]; int ix[5];
#pragma unroll
    for (int p = 0; p < 5; p++) { v[p] = NEGINF; ix[p] = 0x7fffffff; }
    float vmin = NEGINF;

    // read selected chunks in ascending order (keeps index tie-break exact)
    unsigned m = sel;
    while (m) {
        int c = __ffs((int)m) - 1;
        m &= m - 1;
        float2 f = *(const float2*)(Ar + c * 64 + 2 * lane);
        if (fmaxf(f.x, f.y) > vmin) {
            ins5(f.x, c * 64 + 2 * lane, v, ix);
            ins5(f.y, c * 64 + 2 * lane + 1, v, ix);
            vmin = v[4];
        }
    }

    // REDUX merge: 5 rounds; min index among equal values
    int wout[5];
    int ptr = 0;
#pragma unroll
    for (int t5 = 0; t5 < 5; t5++) {
        float hv; int hi;
        head5(v, ix, ptr, hv, hi);
        unsigned key = ordf(hv);
        unsigned mx = __reduce_max_sync(0xffffffffu, key);
        // among lanes with key==mx pick the one with smallest index
        unsigned imin = __reduce_min_sync(0xffffffffu,
                                          (key == mx) ? (unsigned)hi : 0xffffffffu);
        wout[t5] = (int)imin;
        if (key == mx && (unsigned)hi == imin) ptr++;
    }

    // gather top-5 mask rows + max
    const int bc = g >> 10;
    const float* mkb = mask + (size_t)bc * (NN * DD);
    float m0 = NEGINF, m1 = NEGINF;
#pragma unroll
    for (int p = 0; p < 5; p++) {
        const float* mr = mkb + (size_t)wout[p] * DD;
        m0 = fmaxf(m0, mr[lane]);
        m1 = fmaxf(m1, mr[lane + 32]);
    }
    outM[(size_t)g * DD + lane]      = m0;
    outM[(size_t)g * DD + lane + 32] = m1;
}

// ---------------------------------------------------------------------------
extern "C" void kernel_launch(void* const* d_in, const int* in_sizes, int n_in,
                              void* d_out, int out_size) {
    (void)in_sizes; (void)n_in; (void)out_size;
    const float* x    = (const float*)d_in[0];
    const float* A    = (const float*)d_in[1];
    const float* mask = (const float*)d_in[2];
    float* outA = (float*)d_out;
    float* outM = outA + (size_t)BB * C1 * NN * NN;

    cudaFuncSetAttribute(k_S4, cudaFuncAttributeMaxDynamicSharedMemorySize, KS4_SMEM);
    cudaFuncSetAttribute(k_mm2, cudaFuncAttributeMaxDynamicSharedMemorySize, KMM2_SMEM);

    k_conv<<<(NX4 + NM4 + 255) / 256, 256>>>(x, mask);
    k_S4<<<dim3(16, 8, BB), 256, KS4_SMEM>>>();
    k_sreduce3<<<BB * NN, 256>>>(A);
    k_mm2<<<dim3(8, 8, BB), 256, KMM2_SMEM>>>(outA);
    k_topk2<<<BB * C1 * NN / 8, 256>>>(outA, mask, outM);
}